// round 9
// baseline (speedup 1.0000x reference)
#include <cuda_runtime.h>
#include <cuda_bf16.h>
#include <cstdint>

#define B_   4
#define N_   40
#define NC   64000      // 40^3
#define RT   256000     // B * N^3
#define WST  136

typedef unsigned long long u64;

// ---------------- scratch (device globals per allocation rules) ------------
__device__ float g_xembed[(size_t)RT * 128];
__device__ float g_sumexp[B_ * 128];
__device__ int   g_len[B_];
__device__ __align__(16) unsigned short g_wT[4][128 * WST];     // Wi1/Wi2 hi,lo [n][k]
__device__ __align__(16) unsigned short g_weT[2][128 * WST];    // We hi,lo [n][k]
__device__ __align__(16) unsigned short g_wo1T[2][256 * 256];   // Wo1 hi,lo [n][k]

// ---------------- helpers ---------------------------------------------------
static __device__ __forceinline__ uint32_t smem_u32(const void* p) {
    uint32_t a;
    asm("{ .reg .u64 t; cvta.to.shared.u64 t, %1; cvt.u32.u64 %0, t; }" : "=r"(a) : "l"(p));
    return a;
}
static __device__ __forceinline__ float bfhi(float f) {
    return __bfloat162float(__float2bfloat16(f));
}
static __device__ __forceinline__ uint32_t pack_bf2(float lo, float hi) {
    __nv_bfloat162 h = __floats2bfloat162_rn(lo, hi);
    return *reinterpret_cast<uint32_t*>(&h);
}
static __device__ __forceinline__ void ldsm_x4(uint32_t a, uint32_t* r) {
    asm volatile("ldmatrix.sync.aligned.m8n8.x4.shared.b16 {%0,%1,%2,%3}, [%4];"
        : "=r"(r[0]), "=r"(r[1]), "=r"(r[2]), "=r"(r[3]) : "r"(a));
}
static __device__ __forceinline__ void mma16816(float* d, const uint32_t* a, const uint32_t* b) {
    asm volatile("mma.sync.aligned.m16n8k16.row.col.f32.bf16.bf16.f32 "
        "{%0,%1,%2,%3}, {%4,%5,%6,%7}, {%8,%9}, {%0,%1,%2,%3};"
        : "+f"(d[0]), "+f"(d[1]), "+f"(d[2]), "+f"(d[3])
        : "r"(a[0]), "r"(a[1]), "r"(a[2]), "r"(a[3]), "r"(b[0]), "r"(b[1]));
}

// ---------------------------------------------------------------------------
// Kernel 0a: mask -> lengths, zero softmax denominators.
// ---------------------------------------------------------------------------
__global__ void k_setup(const unsigned char* __restrict__ mraw) {
    int t = threadIdx.x;
    if (t < B_ * 128) g_sumexp[t] = 0.f;
    if (t < B_) {
        int cnt = 0;
        if (mraw[1] != 0) {
            for (int j = 0; j < N_; j++) cnt += (mraw[t * N_ + j] != 0) ? 1 : 0;
        } else {
            const unsigned int* mi = (const unsigned int*)mraw;
            for (int j = 0; j < N_; j++) cnt += (mi[t * N_ + j] != 0u) ? 1 : 0;
        }
        g_len[t] = cnt;
    }
}

// ---------------------------------------------------------------------------
// Kernel 0b: transposed bf16 hi/lo weight images for Wi1, Wi2, We, Wo1.
// ---------------------------------------------------------------------------
__global__ void k_prep(const float* __restrict__ Wi1, const float* __restrict__ Wi2,
                       const float* __restrict__ We,  const float* __restrict__ Wo1) {
    int idx = blockIdx.x * 256 + threadIdx.x;
    if (idx < 4 * 128 * WST) {
        int mat = idx / (128 * WST);
        int r   = idx % (128 * WST);
        int n   = r / WST;
        int k   = r % WST;
        float v = 0.f;
        if (k < 128) {
            v = (mat < 2 ? Wi1 : Wi2)[k * 128 + n];
            if (mat & 1) v = v - bfhi(v);
        }
        __nv_bfloat16 h = __float2bfloat16(v);
        g_wT[mat][n * WST + k] = *reinterpret_cast<unsigned short*>(&h);
    } else if (idx < 6 * 128 * WST) {
        int r   = idx - 4 * 128 * WST;
        int img = r / (128 * WST);
        int rr  = r % (128 * WST);
        int n   = rr / WST;
        int k   = rr % WST;
        float v = 0.f;
        if (k < 128) {
            v = We[k * 128 + n];
            if (img) v = v - bfhi(v);
        }
        __nv_bfloat16 h = __float2bfloat16(v);
        g_weT[img][n * WST + k] = *reinterpret_cast<unsigned short*>(&h);
    } else if (idx < 6 * 128 * WST + 2 * 65536) {
        int r   = idx - 6 * 128 * WST;
        int img = r / 65536;
        int rr  = r % 65536;
        int n   = rr / 256;
        int k   = rr % 256;
        float v = Wo1[k * 256 + n];
        if (img) v = v - bfhi(v);
        __nv_bfloat16 h = __float2bfloat16(v);
        g_wo1T[img][n * 256 + k] = *reinterpret_cast<unsigned short*>(&h);
    }
}

// ---------------------------------------------------------------------------
// Kernel 1 (HMMA, unchanged from round 8): x_embed + sumexp.
// ---------------------------------------------------------------------------
#define AHI_OFF 0
#define ALO_OFF 34816
#define W_OFF   69632
#define WIMG    34816
#define SXF_STRIDE 132
#define DSMEM   208896

extern __shared__ unsigned char sdyn[];
__global__ __launch_bounds__(256, 1) void k_embed_hmma(
    const float* __restrict__ x,
    const float* __restrict__ bi1, const float* __restrict__ bi2)
{
    __shared__ float s_bias1[128], s_bias2[128];
    __shared__ unsigned char s_vf[128];

    const int t    = threadIdx.x;
    const int lane = t & 31;
    const int w    = t >> 5;
    const int row0 = blockIdx.x * 128;
    const int b    = row0 / NC;
    const uint32_t sbase = smem_u32(sdyn);

    {
        const float4* ws = (const float4*)g_wT;
        float4* wd = (float4*)(sdyn + W_OFF);
        #pragma unroll
        for (int i = 0; i < 34; i++) wd[t + i * 256] = ws[t + i * 256];
    }
    {
        const float4* xg = (const float4*)(x + (size_t)row0 * 128);
        #pragma unroll
        for (int i = 0; i < 16; i++) {
            int fidx = t + i * 256;
            float4 v = xg[fidx];
            int row = fidx >> 5;
            int k   = (fidx & 31) * 4;
            uint32_t hA = pack_bf2(v.x, v.y);
            uint32_t hB = pack_bf2(v.z, v.w);
            uint32_t lA = pack_bf2(v.x - bfhi(v.x), v.y - bfhi(v.y));
            uint32_t lB = pack_bf2(v.z - bfhi(v.z), v.w - bfhi(v.w));
            size_t off = ((size_t)row * WST + k) * 2;
            *(u64*)(sdyn + AHI_OFF + off) = ((u64)hB << 32) | hA;
            *(u64*)(sdyn + ALO_OFF + off) = ((u64)lB << 32) | lA;
        }
    }
    if (t < 128) {
        s_bias1[t] = bi1[t];
        s_bias2[t] = bi2[t];
        const int lenb = g_len[b];
        const int rem = row0 + t - b * NC;
        const int i  = rem / 1600;
        const int j  = (rem / 40) % 40;
        const int kk = rem % 40;
        s_vf[t] = (i < j) && (j < kk) && (kk < lenb);
    }
    __syncthreads();

    const int m0 = w * 16;
    const int c2 = (lane & 3) * 2;
    const uint32_t aHi = sbase + AHI_OFF + (((m0 + (lane & 15)) * WST + (lane >> 4) * 8) << 1);
    const uint32_t aLo = aHi + (ALO_OFF - AHI_OFF);
    const uint32_t bPr = sbase + W_OFF +
        (((((lane & 7) + ((lane >> 4) << 3)) * WST) + ((lane >> 3) & 1) * 8) << 1);

    float acc[16][4];
    #pragma unroll
    for (int nt = 0; nt < 16; nt++)
        acc[nt][0] = acc[nt][1] = acc[nt][2] = acc[nt][3] = 0.f;

    #pragma unroll
    for (int ks = 0; ks < 8; ks++) {
        uint32_t ahi[4], alo[4];
        ldsm_x4(aHi + ks * 32, ahi);
        ldsm_x4(aLo + ks * 32, alo);
        #pragma unroll
        for (int nt = 0; nt < 16; nt += 2) {
            uint32_t bh[4], bl[4];
            ldsm_x4(bPr + 0 * WIMG + nt * (8 * WST * 2) + ks * 32, bh);
            ldsm_x4(bPr + 1 * WIMG + nt * (8 * WST * 2) + ks * 32, bl);
            mma16816(acc[nt], ahi, bh);     mma16816(acc[nt + 1], ahi, bh + 2);
            mma16816(acc[nt], ahi, bl);     mma16816(acc[nt + 1], ahi, bl + 2);
            mma16816(acc[nt], alo, bh);     mma16816(acc[nt + 1], alo, bh + 2);
        }
    }
    __syncthreads();

    uint32_t a2h[8][4], a2l[8][4];
    #pragma unroll
    for (int ks = 0; ks < 8; ks++) {
        #pragma unroll
        for (int h = 0; h < 2; h++) {
            const int nt = 2 * ks + h;
            const float b0 = s_bias1[nt * 8 + c2];
            const float b1 = s_bias1[nt * 8 + c2 + 1];
            float f0 = fmaxf(acc[nt][0] + b0, 0.f);
            float f1 = fmaxf(acc[nt][1] + b1, 0.f);
            float f2 = fmaxf(acc[nt][2] + b0, 0.f);
            float f3 = fmaxf(acc[nt][3] + b1, 0.f);
            a2h[ks][0 + 2 * h] = pack_bf2(f0, f1);
            a2h[ks][1 + 2 * h] = pack_bf2(f2, f3);
            a2l[ks][0 + 2 * h] = pack_bf2(f0 - bfhi(f0), f1 - bfhi(f1));
            a2l[ks][1 + 2 * h] = pack_bf2(f2 - bfhi(f2), f3 - bfhi(f3));
        }
    }

    #pragma unroll
    for (int nt = 0; nt < 16; nt++)
        acc[nt][0] = acc[nt][1] = acc[nt][2] = acc[nt][3] = 0.f;
    #pragma unroll
    for (int ks = 0; ks < 8; ks++) {
        #pragma unroll
        for (int nt = 0; nt < 16; nt += 2) {
            uint32_t bh[4], bl[4];
            ldsm_x4(bPr + 2 * WIMG + nt * (8 * WST * 2) + ks * 32, bh);
            ldsm_x4(bPr + 3 * WIMG + nt * (8 * WST * 2) + ks * 32, bl);
            mma16816(acc[nt], a2h[ks], bh); mma16816(acc[nt + 1], a2h[ks], bh + 2);
            mma16816(acc[nt], a2h[ks], bl); mma16816(acc[nt + 1], a2h[ks], bl + 2);
            mma16816(acc[nt], a2l[ks], bh); mma16816(acc[nt + 1], a2l[ks], bh + 2);
        }
    }

    float* sxf = (float*)sdyn;
    const int g = lane >> 2;
    #pragma unroll
    for (int nt = 0; nt < 16; nt++) {
        const int nc = nt * 8 + c2;
        const float b0 = s_bias2[nc], b1 = s_bias2[nc + 1];
        *(float2*)(&sxf[(m0 + g) * SXF_STRIDE + nc])     = make_float2(acc[nt][0] + b0, acc[nt][1] + b1);
        *(float2*)(&sxf[(m0 + g + 8) * SXF_STRIDE + nc]) = make_float2(acc[nt][2] + b0, acc[nt][3] + b1);
    }
    __syncthreads();

    {
        float4* xo = (float4*)(g_xembed + (size_t)row0 * 128);
        #pragma unroll
        for (int i = 0; i < 16; i++) {
            int idx = t + i * 256;
            int row = idx >> 5;
            int c4  = (idx & 31) * 4;
            const float* p = &sxf[row * SXF_STRIDE + c4];
            xo[idx] = make_float4(p[0], p[1], p[2], p[3]);
        }
    }
    if (t < 128) {
        float s = 0.f;
        for (int r = 0; r < 128; r++)
            if (s_vf[r]) s += __expf(sxf[r * SXF_STRIDE + t]);
        if (s != 0.f) atomicAdd(&g_sumexp[b * 128 + t], s);
    }
}

// ---------------------------------------------------------------------------
// Kernel 2 (HMMA): out = relu([a*relu(xf@We), xf]@Wo1+bo1)@Wo2+bo2
// Stage A: ks-outer, 16 interleaved accumulators, A loaded 2x per ks.
// xf and axi A-fragments then persist in registers; stage-B inner loops are
// pure-B ldmatrix. Wo1 half-buffers overlay AX/WE smem (XF region stays live
// only for the stage-A epilogue reads, which precede the overlay).
// ---------------------------------------------------------------------------
#define XFHI 0
#define XFLO 34816
#define AXHI 69632
#define AXLO 104448
#define WEHI 139264
#define WELO 174080
#define WO1HI 69632
#define WO1LO 137216     // 69632 + 128*264*2

__global__ __launch_bounds__(256, 1) void k_out_hmma(
    const float* __restrict__ bo1,
    const float* __restrict__ Wo2, const float* __restrict__ bo2,
    float* __restrict__ out)
{
    __shared__ float s_bo1[256], s_wo2[256], s_inv[128];
    __shared__ unsigned char s_vf[128];

    const int t    = threadIdx.x;
    const int lane = t & 31;
    const int w    = t >> 5;
    const int row0 = blockIdx.x * 128;
    const int b    = row0 / NC;
    const uint32_t sbase = smem_u32(sdyn);

    if (t < 128) {
        s_inv[t] = 1.0f / g_sumexp[b * 128 + t];
        const int lenb = g_len[b];
        const int rem = row0 + t - b * NC;
        const int i  = rem / 1600;
        const int j  = (rem / 40) % 40;
        const int kk = rem % 40;
        s_vf[t] = (i < j) && (j < kk) && (kk < lenb);
    }
    s_bo1[t] = bo1[t];
    s_wo2[t] = Wo2[t];
    const int bany = __syncthreads_or((t < 128) ? (int)s_vf[t] : 0);

    // xf tile -> bf16 hi/lo images
    {
        const float4* xg = (const float4*)(g_xembed + (size_t)row0 * 128);
        #pragma unroll
        for (int i = 0; i < 16; i++) {
            int fidx = t + i * 256;
            float4 v = xg[fidx];
            int row = fidx >> 5;
            int k   = (fidx & 31) * 4;
            uint32_t hA = pack_bf2(v.x, v.y);
            uint32_t hB = pack_bf2(v.z, v.w);
            uint32_t lA = pack_bf2(v.x - bfhi(v.x), v.y - bfhi(v.y));
            uint32_t lB = pack_bf2(v.z - bfhi(v.z), v.w - bfhi(v.w));
            size_t off = ((size_t)row * WST + k) * 2;
            *(u64*)(sdyn + XFHI + off) = ((u64)hB << 32) | hA;
            *(u64*)(sdyn + XFLO + off) = ((u64)lB << 32) | lA;
        }
    }
    if (bany) {
        const float4* ws = (const float4*)g_weT;
        float4* wd = (float4*)(sdyn + WEHI);
        #pragma unroll
        for (int i = 0; i < 17; i++) wd[t + i * 256] = ws[t + i * 256];
    }
    __syncthreads();

    const int m0 = w * 16;
    const int c2 = (lane & 3) * 2;
    const int g  = lane >> 2;
    const uint32_t aAddr = sbase + (((m0 + (lane & 15)) * WST + (lane >> 4) * 8) << 1);
    const uint32_t bPr136 = sbase +
        (((((lane & 7) + ((lane >> 4) << 3)) * WST) + ((lane >> 3) & 1) * 8) << 1);

    const int vlane = s_vf[m0 + (lane & 15)];
    const int warp_any = __any_sync(0xffffffffu, vlane);

    // ---- stage A: axi = a .* relu(xf @ We); ks-outer, 16 interleaved accs ----
    uint32_t axh[8][4], axl[8][4];
    if (warp_any) {
        float acc[16][4];
        #pragma unroll
        for (int nt = 0; nt < 16; nt++)
            acc[nt][0] = acc[nt][1] = acc[nt][2] = acc[nt][3] = 0.f;
        #pragma unroll
        for (int ks = 0; ks < 8; ks++) {
            uint32_t ah[4], al[4];
            ldsm_x4(aAddr + XFHI + ks * 32, ah);
            ldsm_x4(aAddr + XFLO + ks * 32, al);
            #pragma unroll
            for (int nt = 0; nt < 16; nt += 2) {
                uint32_t bh[4], bl[4];
                ldsm_x4(bPr136 + WEHI + nt * (8 * WST * 2) + ks * 32, bh);
                ldsm_x4(bPr136 + WELO + nt * (8 * WST * 2) + ks * 32, bl);
                mma16816(acc[nt], ah, bh);  mma16816(acc[nt + 1], ah, bh + 2);
                mma16816(acc[nt], ah, bl);  mma16816(acc[nt + 1], ah, bl + 2);
                mma16816(acc[nt], al, bh);  mma16816(acc[nt + 1], al, bh + 2);
            }
        }
        const int r0 = m0 + g, r1 = m0 + g + 8;
        const bool v0 = s_vf[r0], v1 = s_vf[r1];
        #pragma unroll
        for (int nt = 0; nt < 16; nt++) {
            const int c = nt * 8 + c2;
            const float i0 = s_inv[c], i1 = s_inv[c + 1];
            float v00 = 0.f, v01 = 0.f, v10 = 0.f, v11 = 0.f;
            if (v0) {
                __nv_bfloat162 h = *(__nv_bfloat162*)(sdyn + XFHI + ((r0 * WST + c) << 1));
                __nv_bfloat162 l = *(__nv_bfloat162*)(sdyn + XFLO + ((r0 * WST + c) << 1));
                float x0 = __bfloat162float(h.x) + __bfloat162float(l.x);
                float x1 = __bfloat162float(h.y) + __bfloat162float(l.y);
                v00 = __expf(x0) * i0 * fmaxf(acc[nt][0], 0.f);
                v01 = __expf(x1) * i1 * fmaxf(acc[nt][1], 0.f);
            }
            if (v1) {
                __nv_bfloat162 h = *(__nv_bfloat162*)(sdyn + XFHI + ((r1 * WST + c) << 1));
                __nv_bfloat162 l = *(__nv_bfloat162*)(sdyn + XFLO + ((r1 * WST + c) << 1));
                float x0 = __bfloat162float(h.x) + __bfloat162float(l.x);
                float x1 = __bfloat162float(h.y) + __bfloat162float(l.y);
                v10 = __expf(x0) * i0 * fmaxf(acc[nt][2], 0.f);
                v11 = __expf(x1) * i1 * fmaxf(acc[nt][3], 0.f);
            }
            *(uint32_t*)(sdyn + AXHI + ((r0 * WST + c) << 1)) = pack_bf2(v00, v01);
            *(uint32_t*)(sdyn + AXLO + ((r0 * WST + c) << 1)) = pack_bf2(v00 - bfhi(v00), v01 - bfhi(v01));
            *(uint32_t*)(sdyn + AXHI + ((r1 * WST + c) << 1)) = pack_bf2(v10, v11);
            *(uint32_t*)(sdyn + AXLO + ((r1 * WST + c) << 1)) = pack_bf2(v10 - bfhi(v10), v11 - bfhi(v11));
        }
        __syncwarp();
        #pragma unroll
        for (int ks = 0; ks < 8; ks++) {
            ldsm_x4(aAddr + AXHI + ks * 32, axh[ks]);
            ldsm_x4(aAddr + AXLO + ks * 32, axl[ks]);
        }
    }

    // ---- persistent xf A-fragments (XF smem region is never overlaid) ----
    uint32_t xfh[8][4], xfl[8][4];
    #pragma unroll
    for (int ks = 0; ks < 8; ks++) {
        ldsm_x4(aAddr + XFHI + ks * 32, xfh[ks]);
        ldsm_x4(aAddr + XFLO + ks * 32, xfl[ks]);
    }

    // ---- stage B: two 128-col halves of Wo1; pure-B inner loads ----
    float rsum0 = 0.f, rsum1 = 0.f;
    const uint32_t bPr264 = sbase +
        (((((lane & 7) + ((lane >> 4) << 3)) * 264) + ((lane >> 3) & 1) * 8) << 1);

    #pragma unroll
    for (int half = 0; half < 2; half++) {
        __syncthreads();   // prior reads of the overlay region complete
        #pragma unroll
        for (int img = 0; img < 2; img++) {
            const uint4* src = (const uint4*)(g_wo1T[img] + (half * 128) * 256);
            const uint32_t dst0 = (img ? WO1LO : WO1HI);
            #pragma unroll
            for (int i = 0; i < 16; i++) {
                int e = t + i * 256;
                int r = e >> 5;
                int kq = (e & 31) * 8;
                *(uint4*)(sdyn + dst0 + ((r * 264 + kq) << 1)) = src[e];
            }
        }
        __syncthreads();

        #pragma unroll
        for (int ntg = 0; ntg < 16; ntg += 4) {
            float acc[4][4];
            #pragma unroll
            for (int q = 0; q < 4; q++)
                acc[q][0] = acc[q][1] = acc[q][2] = acc[q][3] = 0.f;
            #pragma unroll
            for (int ks = 0; ks < 8; ks++) {
                // xf part: Wo1 rows k = 128 + ks*16
                {
                    uint32_t bhA[4], bhB[4], blA[4], blB[4];
                    const uint32_t ko = (128 + ks * 16) * 2;
                    ldsm_x4(bPr264 + WO1HI + (ntg + 0) * (8 * 264 * 2) + ko, bhA);
                    ldsm_x4(bPr264 + WO1HI + (ntg + 2) * (8 * 264 * 2) + ko, bhB);
                    ldsm_x4(bPr264 + WO1LO + (ntg + 0) * (8 * 264 * 2) + ko, blA);
                    ldsm_x4(bPr264 + WO1LO + (ntg + 2) * (8 * 264 * 2) + ko, blB);
                    mma16816(acc[0], xfh[ks], bhA);  mma16816(acc[1], xfh[ks], bhA + 2);
                    mma16816(acc[2], xfh[ks], bhB);  mma16816(acc[3], xfh[ks], bhB + 2);
                    mma16816(acc[0], xfh[ks], blA);  mma16816(acc[1], xfh[ks], blA + 2);
                    mma16816(acc[2], xfh[ks], blB);  mma16816(acc[3], xfh[ks], blB + 2);
                    mma16816(acc[0], xfl[ks], bhA);  mma16816(acc[1], xfl[ks], bhA + 2);
                    mma16816(acc[2], xfl[ks], bhB);  mma16816(acc[3], xfl[ks], bhB + 2);
                }
                // a*x_inner part: Wo1 rows k = ks*16 (warp-uniform skip)
                if (warp_any) {
                    uint32_t bhA[4], bhB[4], blA[4], blB[4];
                    const uint32_t ko = (ks * 16) * 2;
                    ldsm_x4(bPr264 + WO1HI + (ntg + 0) * (8 * 264 * 2) + ko, bhA);
                    ldsm_x4(bPr264 + WO1HI + (ntg + 2) * (8 * 264 * 2) + ko, bhB);
                    ldsm_x4(bPr264 + WO1LO + (ntg + 0) * (8 * 264 * 2) + ko, blA);
                    ldsm_x4(bPr264 + WO1LO + (ntg + 2) * (8 * 264 * 2) + ko, blB);
                    mma16816(acc[0], axh[ks], bhA);  mma16816(acc[1], axh[ks], bhA + 2);
                    mma16816(acc[2], axh[ks], bhB);  mma16816(acc[3], axh[ks], bhB + 2);
                    mma16816(acc[0], axh[ks], blA);  mma16816(acc[1], axh[ks], blA + 2);
                    mma16816(acc[2], axh[ks], blB);  mma16816(acc[3], axh[ks], blB + 2);
                    mma16816(acc[0], axl[ks], bhA);  mma16816(acc[1], axl[ks], bhA + 2);
                    mma16816(acc[2], axl[ks], bhB);  mma16816(acc[3], axl[ks], bhB + 2);
                }
            }
            #pragma unroll
            for (int q = 0; q < 4; q++) {
                const int col = half * 128 + (ntg + q) * 8 + c2;
                const float g0 = fmaxf(acc[q][0] + s_bo1[col],     0.f);
                const float g1 = fmaxf(acc[q][1] + s_bo1[col + 1], 0.f);
                const float g2 = fmaxf(acc[q][2] + s_bo1[col],     0.f);
                const float g3 = fmaxf(acc[q][3] + s_bo1[col + 1], 0.f);
                rsum0 += g0 * s_wo2[col] + g1 * s_wo2[col + 1];
                rsum1 += g2 * s_wo2[col] + g3 * s_wo2[col + 1];
            }
        }
    }

    rsum0 += __shfl_xor_sync(0xffffffffu, rsum0, 1);
    rsum0 += __shfl_xor_sync(0xffffffffu, rsum0, 2);
    rsum1 += __shfl_xor_sync(0xffffffffu, rsum1, 1);
    rsum1 += __shfl_xor_sync(0xffffffffu, rsum1, 2);
    if ((lane & 3) == 0) {
        const float b2 = bo2[0];
        out[row0 + m0 + g]     = rsum0 + b2;
        out[row0 + m0 + g + 8] = rsum1 + b2;
    }
}

// ---------------------------------------------------------------------------
extern "C" void kernel_launch(void* const* d_in, const int* in_sizes, int n_in,
                              void* d_out, int out_size) {
    const float* x          = (const float*)d_in[0];
    const unsigned char* mk = (const unsigned char*)d_in[1];
    const float* Wi1        = (const float*)d_in[2];
    const float* bi1        = (const float*)d_in[3];
    const float* Wi2        = (const float*)d_in[4];
    const float* bi2        = (const float*)d_in[5];
    const float* We         = (const float*)d_in[6];
    const float* Wo1        = (const float*)d_in[7];
    const float* bo1        = (const float*)d_in[8];
    const float* Wo2        = (const float*)d_in[9];
    const float* bo2        = (const float*)d_in[10];
    float* out              = (float*)d_out;

    cudaFuncSetAttribute(k_embed_hmma, cudaFuncAttributeMaxDynamicSharedMemorySize, DSMEM);
    cudaFuncSetAttribute(k_out_hmma, cudaFuncAttributeMaxDynamicSharedMemorySize, DSMEM);

    const int prep_elems = 6 * 128 * WST + 2 * 65536;
    k_setup<<<1, 512>>>(mk);
    k_prep<<<(prep_elems + 255) / 256, 256>>>(Wi1, Wi2, We, Wo1);
    k_embed_hmma<<<RT / 128, 256, DSMEM>>>(x, bi1, bi2);
    k_out_hmma<<<RT / 128, 256, DSMEM>>>(bo1, Wo2, bo2, out);
}

// round 10
// speedup vs baseline: 1.3713x; 1.3713x over previous
#include <cuda_runtime.h>
#include <cuda_bf16.h>
#include <cstdint>

#define B_   4
#define N_   40
#define NC   64000      // 40^3
#define RT   256000     // B * N^3
#define WST  136

typedef unsigned long long u64;

// ---------------- scratch (device globals per allocation rules) ------------
__device__ float g_xembed[(size_t)RT * 128];
__device__ float g_sumexp[B_ * 128];
__device__ int   g_len[B_];
__device__ __align__(16) unsigned short g_wT[4][128 * WST];     // Wi1/Wi2 hi,lo [n][k]
__device__ __align__(16) unsigned short g_weT[2][128 * WST];    // We hi,lo [n][k]
__device__ __align__(16) unsigned short g_wo1T[2][256 * 256];   // Wo1 hi,lo [n][k]

// ---------------- helpers ---------------------------------------------------
static __device__ __forceinline__ uint32_t smem_u32(const void* p) {
    uint32_t a;
    asm("{ .reg .u64 t; cvta.to.shared.u64 t, %1; cvt.u32.u64 %0, t; }" : "=r"(a) : "l"(p));
    return a;
}
static __device__ __forceinline__ float bfhi(float f) {
    return __bfloat162float(__float2bfloat16(f));
}
static __device__ __forceinline__ uint32_t pack_bf2(float lo, float hi) {
    __nv_bfloat162 h = __floats2bfloat162_rn(lo, hi);
    return *reinterpret_cast<uint32_t*>(&h);
}
static __device__ __forceinline__ void ldsm_x4(uint32_t a, uint32_t* r) {
    asm volatile("ldmatrix.sync.aligned.m8n8.x4.shared.b16 {%0,%1,%2,%3}, [%4];"
        : "=r"(r[0]), "=r"(r[1]), "=r"(r[2]), "=r"(r[3]) : "r"(a));
}
static __device__ __forceinline__ void mma16816(float* d, const uint32_t* a, const uint32_t* b) {
    asm volatile("mma.sync.aligned.m16n8k16.row.col.f32.bf16.bf16.f32 "
        "{%0,%1,%2,%3}, {%4,%5,%6,%7}, {%8,%9}, {%0,%1,%2,%3};"
        : "+f"(d[0]), "+f"(d[1]), "+f"(d[2]), "+f"(d[3])
        : "r"(a[0]), "r"(a[1]), "r"(a[2]), "r"(a[3]), "r"(b[0]), "r"(b[1]));
}

// ---------------------------------------------------------------------------
// Kernel 0a: mask -> lengths, zero softmax denominators.
// ---------------------------------------------------------------------------
__global__ void k_setup(const unsigned char* __restrict__ mraw) {
    int t = threadIdx.x;
    if (t < B_ * 128) g_sumexp[t] = 0.f;
    if (t < B_) {
        int cnt = 0;
        if (mraw[1] != 0) {
            for (int j = 0; j < N_; j++) cnt += (mraw[t * N_ + j] != 0) ? 1 : 0;
        } else {
            const unsigned int* mi = (const unsigned int*)mraw;
            for (int j = 0; j < N_; j++) cnt += (mi[t * N_ + j] != 0u) ? 1 : 0;
        }
        g_len[t] = cnt;
    }
}

// ---------------------------------------------------------------------------
// Kernel 0b: transposed bf16 hi/lo weight images for Wi1, Wi2, We, Wo1.
// ---------------------------------------------------------------------------
__global__ void k_prep(const float* __restrict__ Wi1, const float* __restrict__ Wi2,
                       const float* __restrict__ We,  const float* __restrict__ Wo1) {
    int idx = blockIdx.x * 256 + threadIdx.x;
    if (idx < 4 * 128 * WST) {
        int mat = idx / (128 * WST);
        int r   = idx % (128 * WST);
        int n   = r / WST;
        int k   = r % WST;
        float v = 0.f;
        if (k < 128) {
            v = (mat < 2 ? Wi1 : Wi2)[k * 128 + n];
            if (mat & 1) v = v - bfhi(v);
        }
        __nv_bfloat16 h = __float2bfloat16(v);
        g_wT[mat][n * WST + k] = *reinterpret_cast<unsigned short*>(&h);
    } else if (idx < 6 * 128 * WST) {
        int r   = idx - 4 * 128 * WST;
        int img = r / (128 * WST);
        int rr  = r % (128 * WST);
        int n   = rr / WST;
        int k   = rr % WST;
        float v = 0.f;
        if (k < 128) {
            v = We[k * 128 + n];
            if (img) v = v - bfhi(v);
        }
        __nv_bfloat16 h = __float2bfloat16(v);
        g_weT[img][n * WST + k] = *reinterpret_cast<unsigned short*>(&h);
    } else if (idx < 6 * 128 * WST + 2 * 65536) {
        int r   = idx - 6 * 128 * WST;
        int img = r / 65536;
        int rr  = r % 65536;
        int n   = rr / 256;
        int k   = rr % 256;
        float v = Wo1[k * 256 + n];
        if (img) v = v - bfhi(v);
        __nv_bfloat16 h = __float2bfloat16(v);
        g_wo1T[img][n * 256 + k] = *reinterpret_cast<unsigned short*>(&h);
    }
}

// ---------------------------------------------------------------------------
// Kernel 1 (HMMA, unchanged from round-8 best): x_embed + sumexp.
// ---------------------------------------------------------------------------
#define AHI_OFF 0
#define ALO_OFF 34816
#define W_OFF   69632
#define WIMG    34816
#define SXF_STRIDE 132
#define DSMEM   208896

extern __shared__ unsigned char sdyn[];
__global__ __launch_bounds__(256, 1) void k_embed_hmma(
    const float* __restrict__ x,
    const float* __restrict__ bi1, const float* __restrict__ bi2)
{
    __shared__ float s_bias1[128], s_bias2[128];
    __shared__ unsigned char s_vf[128];

    const int t    = threadIdx.x;
    const int lane = t & 31;
    const int w    = t >> 5;
    const int row0 = blockIdx.x * 128;
    const int b    = row0 / NC;
    const uint32_t sbase = smem_u32(sdyn);

    {
        const float4* ws = (const float4*)g_wT;
        float4* wd = (float4*)(sdyn + W_OFF);
        #pragma unroll
        for (int i = 0; i < 34; i++) wd[t + i * 256] = ws[t + i * 256];
    }
    {
        const float4* xg = (const float4*)(x + (size_t)row0 * 128);
        #pragma unroll
        for (int i = 0; i < 16; i++) {
            int fidx = t + i * 256;
            float4 v = xg[fidx];
            int row = fidx >> 5;
            int k   = (fidx & 31) * 4;
            uint32_t hA = pack_bf2(v.x, v.y);
            uint32_t hB = pack_bf2(v.z, v.w);
            uint32_t lA = pack_bf2(v.x - bfhi(v.x), v.y - bfhi(v.y));
            uint32_t lB = pack_bf2(v.z - bfhi(v.z), v.w - bfhi(v.w));
            size_t off = ((size_t)row * WST + k) * 2;
            *(u64*)(sdyn + AHI_OFF + off) = ((u64)hB << 32) | hA;
            *(u64*)(sdyn + ALO_OFF + off) = ((u64)lB << 32) | lA;
        }
    }
    if (t < 128) {
        s_bias1[t] = bi1[t];
        s_bias2[t] = bi2[t];
        const int lenb = g_len[b];
        const int rem = row0 + t - b * NC;
        const int i  = rem / 1600;
        const int j  = (rem / 40) % 40;
        const int kk = rem % 40;
        s_vf[t] = (i < j) && (j < kk) && (kk < lenb);
    }
    __syncthreads();

    const int m0 = w * 16;
    const int c2 = (lane & 3) * 2;
    const uint32_t aHi = sbase + AHI_OFF + (((m0 + (lane & 15)) * WST + (lane >> 4) * 8) << 1);
    const uint32_t aLo = aHi + (ALO_OFF - AHI_OFF);
    const uint32_t bPr = sbase + W_OFF +
        (((((lane & 7) + ((lane >> 4) << 3)) * WST) + ((lane >> 3) & 1) * 8) << 1);

    float acc[16][4];
    #pragma unroll
    for (int nt = 0; nt < 16; nt++)
        acc[nt][0] = acc[nt][1] = acc[nt][2] = acc[nt][3] = 0.f;

    #pragma unroll
    for (int ks = 0; ks < 8; ks++) {
        uint32_t ahi[4], alo[4];
        ldsm_x4(aHi + ks * 32, ahi);
        ldsm_x4(aLo + ks * 32, alo);
        #pragma unroll
        for (int nt = 0; nt < 16; nt += 2) {
            uint32_t bh[4], bl[4];
            ldsm_x4(bPr + 0 * WIMG + nt * (8 * WST * 2) + ks * 32, bh);
            ldsm_x4(bPr + 1 * WIMG + nt * (8 * WST * 2) + ks * 32, bl);
            mma16816(acc[nt], ahi, bh);     mma16816(acc[nt + 1], ahi, bh + 2);
            mma16816(acc[nt], ahi, bl);     mma16816(acc[nt + 1], ahi, bl + 2);
            mma16816(acc[nt], alo, bh);     mma16816(acc[nt + 1], alo, bh + 2);
        }
    }
    __syncthreads();

    uint32_t a2h[8][4], a2l[8][4];
    #pragma unroll
    for (int ks = 0; ks < 8; ks++) {
        #pragma unroll
        for (int h = 0; h < 2; h++) {
            const int nt = 2 * ks + h;
            const float b0 = s_bias1[nt * 8 + c2];
            const float b1 = s_bias1[nt * 8 + c2 + 1];
            float f0 = fmaxf(acc[nt][0] + b0, 0.f);
            float f1 = fmaxf(acc[nt][1] + b1, 0.f);
            float f2 = fmaxf(acc[nt][2] + b0, 0.f);
            float f3 = fmaxf(acc[nt][3] + b1, 0.f);
            a2h[ks][0 + 2 * h] = pack_bf2(f0, f1);
            a2h[ks][1 + 2 * h] = pack_bf2(f2, f3);
            a2l[ks][0 + 2 * h] = pack_bf2(f0 - bfhi(f0), f1 - bfhi(f1));
            a2l[ks][1 + 2 * h] = pack_bf2(f2 - bfhi(f2), f3 - bfhi(f3));
        }
    }

    #pragma unroll
    for (int nt = 0; nt < 16; nt++)
        acc[nt][0] = acc[nt][1] = acc[nt][2] = acc[nt][3] = 0.f;
    #pragma unroll
    for (int ks = 0; ks < 8; ks++) {
        #pragma unroll
        for (int nt = 0; nt < 16; nt += 2) {
            uint32_t bh[4], bl[4];
            ldsm_x4(bPr + 2 * WIMG + nt * (8 * WST * 2) + ks * 32, bh);
            ldsm_x4(bPr + 3 * WIMG + nt * (8 * WST * 2) + ks * 32, bl);
            mma16816(acc[nt], a2h[ks], bh); mma16816(acc[nt + 1], a2h[ks], bh + 2);
            mma16816(acc[nt], a2h[ks], bl); mma16816(acc[nt + 1], a2h[ks], bl + 2);
            mma16816(acc[nt], a2l[ks], bh); mma16816(acc[nt + 1], a2l[ks], bh + 2);
        }
    }

    float* sxf = (float*)sdyn;
    const int g = lane >> 2;
    #pragma unroll
    for (int nt = 0; nt < 16; nt++) {
        const int nc = nt * 8 + c2;
        const float b0 = s_bias2[nc], b1 = s_bias2[nc + 1];
        *(float2*)(&sxf[(m0 + g) * SXF_STRIDE + nc])     = make_float2(acc[nt][0] + b0, acc[nt][1] + b1);
        *(float2*)(&sxf[(m0 + g + 8) * SXF_STRIDE + nc]) = make_float2(acc[nt][2] + b0, acc[nt][3] + b1);
    }
    __syncthreads();

    {
        float4* xo = (float4*)(g_xembed + (size_t)row0 * 128);
        #pragma unroll
        for (int i = 0; i < 16; i++) {
            int idx = t + i * 256;
            int row = idx >> 5;
            int c4  = (idx & 31) * 4;
            const float* p = &sxf[row * SXF_STRIDE + c4];
            xo[idx] = make_float4(p[0], p[1], p[2], p[3]);
        }
    }
    if (t < 128) {
        float s = 0.f;
        for (int r = 0; r < 128; r++)
            if (s_vf[r]) s += __expf(sxf[r * SXF_STRIDE + t]);
        if (s != 0.f) atomicAdd(&g_sumexp[b * 128 + t], s);
    }
}

// ---------------------------------------------------------------------------
// Kernel 2 (HMMA v3): warp = M64 x N64(stage B)/N32(stage A);
// B fragments loaded straight from global ([n][k] images) as 32-bit words;
// A fragments via ldmatrix from XF/AX smem. No Wo1 smem staging, no spills.
// ---------------------------------------------------------------------------
#define XFHI 0
#define XFLO 34816
#define AXHI 69632
#define AXLO 104448
#define DSMEM_OUT 139264

__global__ __launch_bounds__(256, 1) void k_out_hmma(
    const float* __restrict__ bo1,
    const float* __restrict__ Wo2, const float* __restrict__ bo2,
    float* __restrict__ out)
{
    __shared__ float s_bo1[256], s_wo2[256], s_inv[128];
    __shared__ float s_part[128 * 4];
    __shared__ unsigned char s_vf[128];

    const int t    = threadIdx.x;
    const int lane = t & 31;
    const int w    = t >> 5;
    const int mg   = w >> 2;          // 0..1 : 64-row group
    const int ng   = w & 3;           // 0..3 : column group
    const int row0 = blockIdx.x * 128;
    const int b    = row0 / NC;
    const uint32_t sbase = smem_u32(sdyn);

    if (t < 128) {
        s_inv[t] = 1.0f / g_sumexp[b * 128 + t];
        const int lenb = g_len[b];
        const int rem = row0 + t - b * NC;
        const int i  = rem / 1600;
        const int j  = (rem / 40) % 40;
        const int kk = rem % 40;
        s_vf[t] = (i < j) && (j < kk) && (kk < lenb);
    }
    s_bo1[t] = bo1[t];
    s_wo2[t] = Wo2[t];

    // xf tile -> bf16 hi/lo images
    {
        const float4* xg = (const float4*)(g_xembed + (size_t)row0 * 128);
        #pragma unroll
        for (int i = 0; i < 16; i++) {
            int fidx = t + i * 256;
            float4 v = xg[fidx];
            int row = fidx >> 5;
            int k   = (fidx & 31) * 4;
            uint32_t hA = pack_bf2(v.x, v.y);
            uint32_t hB = pack_bf2(v.z, v.w);
            uint32_t lA = pack_bf2(v.x - bfhi(v.x), v.y - bfhi(v.y));
            uint32_t lB = pack_bf2(v.z - bfhi(v.z), v.w - bfhi(v.w));
            size_t off = ((size_t)row * WST + k) * 2;
            *(u64*)(sdyn + XFHI + off) = ((u64)hB << 32) | hA;
            *(u64*)(sdyn + XFLO + off) = ((u64)lB << 32) | lA;
        }
    }
    __syncthreads();

    const int c2 = (lane & 3) * 2;
    const int g  = lane >> 2;
    // A-frag smem addresses per m-tile (rows mg*64 + mt*16)
    uint32_t aXF[4];
    #pragma unroll
    for (int mt = 0; mt < 4; mt++)
        aXF[mt] = sbase + XFHI + (((mg * 64 + mt * 16 + (lane & 15)) * WST + (lane >> 4) * 8) << 1);

    // B LDG lane indices
    const int bn   = lane >> 2;          // n offset within 8-wide tile
    const int bk   = (lane & 3) * 2;     // k offset within 16-wide step

    // warp-uniform validity over this warp's 64 rows
    const int vl = (int)s_vf[mg * 64 + lane] | (int)s_vf[mg * 64 + 64 - 32 + lane - (lane & 31) + (lane)];
    // (simple form below)
    const int vlane = (int)s_vf[mg * 64 + lane] | (int)s_vf[mg * 64 + 32 + lane];
    const int warp_any = __any_sync(0xffffffffu, vlane);
    (void)vl;

    // ---- stage A: axi = a .* relu(xf @ We); warp covers M64 x N32 ----
    if (warp_any) {
        float acc[4][4][4];
        #pragma unroll
        for (int mt = 0; mt < 4; mt++)
            #pragma unroll
            for (int nt = 0; nt < 4; nt++)
                acc[mt][nt][0] = acc[mt][nt][1] = acc[mt][nt][2] = acc[mt][nt][3] = 0.f;

        #pragma unroll
        for (int ks = 0; ks < 8; ks++) {
            uint32_t ah[4][4], al[4][4];
            #pragma unroll
            for (int mt = 0; mt < 4; mt++) {
                ldsm_x4(aXF[mt] + ks * 32, ah[mt]);
                ldsm_x4(aXF[mt] + (XFLO - XFHI) + ks * 32, al[mt]);
            }
            const int k0 = ks * 16 + bk;
            uint32_t bh[4][2], bl[4][2];
            #pragma unroll
            for (int nt = 0; nt < 4; nt++) {
                const int n = ng * 32 + nt * 8 + bn;
                const unsigned short* ph = g_weT[0] + n * WST + k0;
                const unsigned short* pl = g_weT[1] + n * WST + k0;
                bh[nt][0] = *(const uint32_t*)ph;
                bh[nt][1] = *(const uint32_t*)(ph + 8);
                bl[nt][0] = *(const uint32_t*)pl;
                bl[nt][1] = *(const uint32_t*)(pl + 8);
            }
            #pragma unroll
            for (int mt = 0; mt < 4; mt++)
                #pragma unroll
                for (int nt = 0; nt < 4; nt++) {
                    mma16816(acc[mt][nt], ah[mt], bh[nt]);
                    mma16816(acc[mt][nt], ah[mt], bl[nt]);
                    mma16816(acc[mt][nt], al[mt], bh[nt]);
                }
        }
        // epilogue: a * relu(acc) -> AX hi/lo images
        #pragma unroll
        for (int mt = 0; mt < 4; mt++) {
            const int r0 = mg * 64 + mt * 16 + g, r1 = r0 + 8;
            const bool v0 = s_vf[r0], v1 = s_vf[r1];
            #pragma unroll
            for (int nt = 0; nt < 4; nt++) {
                const int c = ng * 32 + nt * 8 + c2;
                const float i0 = s_inv[c], i1 = s_inv[c + 1];
                float v00 = 0.f, v01 = 0.f, v10 = 0.f, v11 = 0.f;
                if (v0) {
                    __nv_bfloat162 h = *(__nv_bfloat162*)(sdyn + XFHI + ((r0 * WST + c) << 1));
                    __nv_bfloat162 l = *(__nv_bfloat162*)(sdyn + XFLO + ((r0 * WST + c) << 1));
                    float x0 = __bfloat162float(h.x) + __bfloat162float(l.x);
                    float x1 = __bfloat162float(h.y) + __bfloat162float(l.y);
                    v00 = __expf(x0) * i0 * fmaxf(acc[mt][nt][0], 0.f);
                    v01 = __expf(x1) * i1 * fmaxf(acc[mt][nt][1], 0.f);
                }
                if (v1) {
                    __nv_bfloat162 h = *(__nv_bfloat162*)(sdyn + XFHI + ((r1 * WST + c) << 1));
                    __nv_bfloat162 l = *(__nv_bfloat162*)(sdyn + XFLO + ((r1 * WST + c) << 1));
                    float x0 = __bfloat162float(h.x) + __bfloat162float(l.x);
                    float x1 = __bfloat162float(h.y) + __bfloat162float(l.y);
                    v10 = __expf(x0) * i0 * fmaxf(acc[mt][nt][2], 0.f);
                    v11 = __expf(x1) * i1 * fmaxf(acc[mt][nt][3], 0.f);
                }
                *(uint32_t*)(sdyn + AXHI + ((r0 * WST + c) << 1)) = pack_bf2(v00, v01);
                *(uint32_t*)(sdyn + AXLO + ((r0 * WST + c) << 1)) = pack_bf2(v00 - bfhi(v00), v01 - bfhi(v01));
                *(uint32_t*)(sdyn + AXHI + ((r1 * WST + c) << 1)) = pack_bf2(v10, v11);
                *(uint32_t*)(sdyn + AXLO + ((r1 * WST + c) << 1)) = pack_bf2(v10 - bfhi(v10), v11 - bfhi(v11));
            }
        }
    }
    __syncthreads();   // AX columns written by all ng warps of this mg

    // ---- stage B: g = relu(h @ Wo1 + bo1); rsum = g @ Wo2 ----
    float rsum0[4], rsum1[4];
    #pragma unroll
    for (int mt = 0; mt < 4; mt++) { rsum0[mt] = 0.f; rsum1[mt] = 0.f; }

    #pragma unroll
    for (int grp = 0; grp < 2; grp++) {
        float acc[4][4][4];
        #pragma unroll
        for (int mt = 0; mt < 4; mt++)
            #pragma unroll
            for (int q = 0; q < 4; q++)
                acc[mt][q][0] = acc[mt][q][1] = acc[mt][q][2] = acc[mt][q][3] = 0.f;

        #pragma unroll
        for (int ks = 0; ks < 8; ks++) {
            const int k0 = ks * 16 + bk;
            // --- xf part: Wo1 rows k = 128 + ks*16 ---
            {
                uint32_t ah[4][4], al[4][4];
                #pragma unroll
                for (int mt = 0; mt < 4; mt++) {
                    ldsm_x4(aXF[mt] + ks * 32, ah[mt]);
                    ldsm_x4(aXF[mt] + (XFLO - XFHI) + ks * 32, al[mt]);
                }
                uint32_t bh[4][2], bl[4][2];
                #pragma unroll
                for (int q = 0; q < 4; q++) {
                    const int n = ng * 64 + grp * 32 + q * 8 + bn;
                    const unsigned short* ph = g_wo1T[0] + n * 256 + 128 + k0;
                    const unsigned short* pl = g_wo1T[1] + n * 256 + 128 + k0;
                    bh[q][0] = *(const uint32_t*)ph;
                    bh[q][1] = *(const uint32_t*)(ph + 8);
                    bl[q][0] = *(const uint32_t*)pl;
                    bl[q][1] = *(const uint32_t*)(pl + 8);
                }
                #pragma unroll
                for (int mt = 0; mt < 4; mt++)
                    #pragma unroll
                    for (int q = 0; q < 4; q++) {
                        mma16816(acc[mt][q], ah[mt], bh[q]);
                        mma16816(acc[mt][q], ah[mt], bl[q]);
                        mma16816(acc[mt][q], al[mt], bh[q]);
                    }
            }
            // --- a*x_inner part: Wo1 rows k = ks*16 (warp-uniform skip) ---
            if (warp_any) {
                uint32_t ah[4][4], al[4][4];
                #pragma unroll
                for (int mt = 0; mt < 4; mt++) {
                    ldsm_x4(aXF[mt] + (AXHI - XFHI) + ks * 32, ah[mt]);
                    ldsm_x4(aXF[mt] + (AXLO - XFHI) + ks * 32, al[mt]);
                }
                uint32_t bh[4][2], bl[4][2];
                #pragma unroll
                for (int q = 0; q < 4; q++) {
                    const int n = ng * 64 + grp * 32 + q * 8 + bn;
                    const unsigned short* ph = g_wo1T[0] + n * 256 + k0;
                    const unsigned short* pl = g_wo1T[1] + n * 256 + k0;
                    bh[q][0] = *(const uint32_t*)ph;
                    bh[q][1] = *(const uint32_t*)(ph + 8);
                    bl[q][0] = *(const uint32_t*)pl;
                    bl[q][1] = *(const uint32_t*)(pl + 8);
                }
                #pragma unroll
                for (int mt = 0; mt < 4; mt++)
                    #pragma unroll
                    for (int q = 0; q < 4; q++) {
                        mma16816(acc[mt][q], ah[mt], bh[q]);
                        mma16816(acc[mt][q], ah[mt], bl[q]);
                        mma16816(acc[mt][q], al[mt], bh[q]);
                    }
            }
        }
        // epilogue: bias + relu + Wo2 dot, accumulate per-row partials
        #pragma unroll
        for (int mt = 0; mt < 4; mt++)
            #pragma unroll
            for (int q = 0; q < 4; q++) {
                const int col = ng * 64 + grp * 32 + q * 8 + c2;
                const float g0 = fmaxf(acc[mt][q][0] + s_bo1[col],     0.f);
                const float g1 = fmaxf(acc[mt][q][1] + s_bo1[col + 1], 0.f);
                const float g2 = fmaxf(acc[mt][q][2] + s_bo1[col],     0.f);
                const float g3 = fmaxf(acc[mt][q][3] + s_bo1[col + 1], 0.f);
                rsum0[mt] += g0 * s_wo2[col] + g1 * s_wo2[col + 1];
                rsum1[mt] += g2 * s_wo2[col] + g3 * s_wo2[col + 1];
            }
    }

    // reduce over the 4 column-lanes, stash per-(row, ng) partials
    #pragma unroll
    for (int mt = 0; mt < 4; mt++) {
        rsum0[mt] += __shfl_xor_sync(0xffffffffu, rsum0[mt], 1);
        rsum0[mt] += __shfl_xor_sync(0xffffffffu, rsum0[mt], 2);
        rsum1[mt] += __shfl_xor_sync(0xffffffffu, rsum1[mt], 1);
        rsum1[mt] += __shfl_xor_sync(0xffffffffu, rsum1[mt], 2);
    }
    if ((lane & 3) == 0) {
        #pragma unroll
        for (int mt = 0; mt < 4; mt++) {
            const int r0 = mg * 64 + mt * 16 + g;
            s_part[r0 * 4 + ng]       = rsum0[mt];
            s_part[(r0 + 8) * 4 + ng] = rsum1[mt];
        }
    }
    __syncthreads();
    if (t < 128) {
        out[row0 + t] = s_part[t * 4 + 0] + s_part[t * 4 + 1]
                      + s_part[t * 4 + 2] + s_part[t * 4 + 3] + bo2[0];
    }
}

// ---------------------------------------------------------------------------
extern "C" void kernel_launch(void* const* d_in, const int* in_sizes, int n_in,
                              void* d_out, int out_size) {
    const float* x          = (const float*)d_in[0];
    const unsigned char* mk = (const unsigned char*)d_in[1];
    const float* Wi1        = (const float*)d_in[2];
    const float* bi1        = (const float*)d_in[3];
    const float* Wi2        = (const float*)d_in[4];
    const float* bi2        = (const float*)d_in[5];
    const float* We         = (const float*)d_in[6];
    const float* Wo1        = (const float*)d_in[7];
    const float* bo1        = (const float*)d_in[8];
    const float* Wo2        = (const float*)d_in[9];
    const float* bo2        = (const float*)d_in[10];
    float* out              = (float*)d_out;

    cudaFuncSetAttribute(k_embed_hmma, cudaFuncAttributeMaxDynamicSharedMemorySize, DSMEM);
    cudaFuncSetAttribute(k_out_hmma, cudaFuncAttributeMaxDynamicSharedMemorySize, DSMEM_OUT);

    const int prep_elems = 6 * 128 * WST + 2 * 65536;
    k_setup<<<1, 512>>>(mk);
    k_prep<<<(prep_elems + 255) / 256, 256>>>(Wi1, Wi2, We, Wo1);
    k_embed_hmma<<<RT / 128, 256, DSMEM>>>(x, bi1, bi2);
    k_out_hmma<<<RT / 128, 256, DSMEM_OUT>>>(bo1, Wo2, bo2, out);
}

// round 11
// speedup vs baseline: 1.5730x; 1.1471x over previous
#include <cuda_runtime.h>
#include <cuda_bf16.h>
#include <cstdint>

#define B_   4
#define N_   40
#define NC   64000      // 40^3
#define RT   256000     // B * N^3
#define WST  136

typedef unsigned long long u64;

// ---------------- scratch (device globals per allocation rules) ------------
__device__ float g_xembed[(size_t)RT * 128];
__device__ float g_sumexp[B_ * 128];
__device__ int   g_len[B_];
__device__ __align__(16) unsigned short g_wT[4][128 * WST];     // Wi1/Wi2 hi,lo [n][k]
__device__ __align__(16) unsigned short g_weT[2][128 * WST];    // We hi,lo [n][k]
__device__ __align__(16) unsigned short g_wo1T[2][256 * 256];   // Wo1 hi,lo [n][k]

// ---------------- helpers ---------------------------------------------------
static __device__ __forceinline__ uint32_t smem_u32(const void* p) {
    uint32_t a;
    asm("{ .reg .u64 t; cvta.to.shared.u64 t, %1; cvt.u32.u64 %0, t; }" : "=r"(a) : "l"(p));
    return a;
}
static __device__ __forceinline__ float bfhi(float f) {
    return __bfloat162float(__float2bfloat16(f));
}
static __device__ __forceinline__ uint32_t pack_bf2(float lo, float hi) {
    __nv_bfloat162 h = __floats2bfloat162_rn(lo, hi);
    return *reinterpret_cast<uint32_t*>(&h);
}
static __device__ __forceinline__ void ldsm_x4(uint32_t a, uint32_t* r) {
    asm volatile("ldmatrix.sync.aligned.m8n8.x4.shared.b16 {%0,%1,%2,%3}, [%4];"
        : "=r"(r[0]), "=r"(r[1]), "=r"(r[2]), "=r"(r[3]) : "r"(a));
}
static __device__ __forceinline__ void mma16816(float* d, const uint32_t* a, const uint32_t* b) {
    asm volatile("mma.sync.aligned.m16n8k16.row.col.f32.bf16.bf16.f32 "
        "{%0,%1,%2,%3}, {%4,%5,%6,%7}, {%8,%9}, {%0,%1,%2,%3};"
        : "+f"(d[0]), "+f"(d[1]), "+f"(d[2]), "+f"(d[3])
        : "r"(a[0]), "r"(a[1]), "r"(a[2]), "r"(a[3]), "r"(b[0]), "r"(b[1]));
}

// ---------------------------------------------------------------------------
// Kernel 0a: mask -> lengths, zero softmax denominators.
// ---------------------------------------------------------------------------
__global__ void k_setup(const unsigned char* __restrict__ mraw) {
    int t = threadIdx.x;
    if (t < B_ * 128) g_sumexp[t] = 0.f;
    if (t < B_) {
        int cnt = 0;
        if (mraw[1] != 0) {
            for (int j = 0; j < N_; j++) cnt += (mraw[t * N_ + j] != 0) ? 1 : 0;
        } else {
            const unsigned int* mi = (const unsigned int*)mraw;
            for (int j = 0; j < N_; j++) cnt += (mi[t * N_ + j] != 0u) ? 1 : 0;
        }
        g_len[t] = cnt;
    }
}

// ---------------------------------------------------------------------------
// Kernel 0b: transposed bf16 hi/lo weight images for Wi1, Wi2, We, Wo1.
// ---------------------------------------------------------------------------
__global__ void k_prep(const float* __restrict__ Wi1, const float* __restrict__ Wi2,
                       const float* __restrict__ We,  const float* __restrict__ Wo1) {
    int idx = blockIdx.x * 256 + threadIdx.x;
    if (idx < 4 * 128 * WST) {
        int mat = idx / (128 * WST);
        int r   = idx % (128 * WST);
        int n   = r / WST;
        int k   = r % WST;
        float v = 0.f;
        if (k < 128) {
            v = (mat < 2 ? Wi1 : Wi2)[k * 128 + n];
            if (mat & 1) v = v - bfhi(v);
        }
        __nv_bfloat16 h = __float2bfloat16(v);
        g_wT[mat][n * WST + k] = *reinterpret_cast<unsigned short*>(&h);
    } else if (idx < 6 * 128 * WST) {
        int r   = idx - 4 * 128 * WST;
        int img = r / (128 * WST);
        int rr  = r % (128 * WST);
        int n   = rr / WST;
        int k   = rr % WST;
        float v = 0.f;
        if (k < 128) {
            v = We[k * 128 + n];
            if (img) v = v - bfhi(v);
        }
        __nv_bfloat16 h = __float2bfloat16(v);
        g_weT[img][n * WST + k] = *reinterpret_cast<unsigned short*>(&h);
    } else if (idx < 6 * 128 * WST + 2 * 65536) {
        int r   = idx - 6 * 128 * WST;
        int img = r / 65536;
        int rr  = r % 65536;
        int n   = rr / 256;
        int k   = rr % 256;
        float v = Wo1[k * 256 + n];
        if (img) v = v - bfhi(v);
        __nv_bfloat16 h = __float2bfloat16(v);
        g_wo1T[img][n * 256 + k] = *reinterpret_cast<unsigned short*>(&h);
    }
}

// ---------------------------------------------------------------------------
// Kernel 1 (HMMA, unchanged from round-8 best): x_embed + sumexp.
// ---------------------------------------------------------------------------
#define AHI_OFF 0
#define ALO_OFF 34816
#define W_OFF   69632
#define WIMG    34816
#define SXF_STRIDE 132
#define DSMEM   208896

extern __shared__ unsigned char sdyn[];
__global__ __launch_bounds__(256, 1) void k_embed_hmma(
    const float* __restrict__ x,
    const float* __restrict__ bi1, const float* __restrict__ bi2)
{
    __shared__ float s_bias1[128], s_bias2[128];
    __shared__ unsigned char s_vf[128];

    const int t    = threadIdx.x;
    const int lane = t & 31;
    const int w    = t >> 5;
    const int row0 = blockIdx.x * 128;
    const int b    = row0 / NC;
    const uint32_t sbase = smem_u32(sdyn);

    {
        const float4* ws = (const float4*)g_wT;
        float4* wd = (float4*)(sdyn + W_OFF);
        #pragma unroll
        for (int i = 0; i < 34; i++) wd[t + i * 256] = ws[t + i * 256];
    }
    {
        const float4* xg = (const float4*)(x + (size_t)row0 * 128);
        #pragma unroll
        for (int i = 0; i < 16; i++) {
            int fidx = t + i * 256;
            float4 v = xg[fidx];
            int row = fidx >> 5;
            int k   = (fidx & 31) * 4;
            uint32_t hA = pack_bf2(v.x, v.y);
            uint32_t hB = pack_bf2(v.z, v.w);
            uint32_t lA = pack_bf2(v.x - bfhi(v.x), v.y - bfhi(v.y));
            uint32_t lB = pack_bf2(v.z - bfhi(v.z), v.w - bfhi(v.w));
            size_t off = ((size_t)row * WST + k) * 2;
            *(u64*)(sdyn + AHI_OFF + off) = ((u64)hB << 32) | hA;
            *(u64*)(sdyn + ALO_OFF + off) = ((u64)lB << 32) | lA;
        }
    }
    if (t < 128) {
        s_bias1[t] = bi1[t];
        s_bias2[t] = bi2[t];
        const int lenb = g_len[b];
        const int rem = row0 + t - b * NC;
        const int i  = rem / 1600;
        const int j  = (rem / 40) % 40;
        const int kk = rem % 40;
        s_vf[t] = (i < j) && (j < kk) && (kk < lenb);
    }
    __syncthreads();

    const int m0 = w * 16;
    const int c2 = (lane & 3) * 2;
    const uint32_t aHi = sbase + AHI_OFF + (((m0 + (lane & 15)) * WST + (lane >> 4) * 8) << 1);
    const uint32_t aLo = aHi + (ALO_OFF - AHI_OFF);
    const uint32_t bPr = sbase + W_OFF +
        (((((lane & 7) + ((lane >> 4) << 3)) * WST) + ((lane >> 3) & 1) * 8) << 1);

    float acc[16][4];
    #pragma unroll
    for (int nt = 0; nt < 16; nt++)
        acc[nt][0] = acc[nt][1] = acc[nt][2] = acc[nt][3] = 0.f;

    #pragma unroll
    for (int ks = 0; ks < 8; ks++) {
        uint32_t ahi[4], alo[4];
        ldsm_x4(aHi + ks * 32, ahi);
        ldsm_x4(aLo + ks * 32, alo);
        #pragma unroll
        for (int nt = 0; nt < 16; nt += 2) {
            uint32_t bh[4], bl[4];
            ldsm_x4(bPr + 0 * WIMG + nt * (8 * WST * 2) + ks * 32, bh);
            ldsm_x4(bPr + 1 * WIMG + nt * (8 * WST * 2) + ks * 32, bl);
            mma16816(acc[nt], ahi, bh);     mma16816(acc[nt + 1], ahi, bh + 2);
            mma16816(acc[nt], ahi, bl);     mma16816(acc[nt + 1], ahi, bl + 2);
            mma16816(acc[nt], alo, bh);     mma16816(acc[nt + 1], alo, bh + 2);
        }
    }
    __syncthreads();

    uint32_t a2h[8][4], a2l[8][4];
    #pragma unroll
    for (int ks = 0; ks < 8; ks++) {
        #pragma unroll
        for (int h = 0; h < 2; h++) {
            const int nt = 2 * ks + h;
            const float b0 = s_bias1[nt * 8 + c2];
            const float b1 = s_bias1[nt * 8 + c2 + 1];
            float f0 = fmaxf(acc[nt][0] + b0, 0.f);
            float f1 = fmaxf(acc[nt][1] + b1, 0.f);
            float f2 = fmaxf(acc[nt][2] + b0, 0.f);
            float f3 = fmaxf(acc[nt][3] + b1, 0.f);
            a2h[ks][0 + 2 * h] = pack_bf2(f0, f1);
            a2h[ks][1 + 2 * h] = pack_bf2(f2, f3);
            a2l[ks][0 + 2 * h] = pack_bf2(f0 - bfhi(f0), f1 - bfhi(f1));
            a2l[ks][1 + 2 * h] = pack_bf2(f2 - bfhi(f2), f3 - bfhi(f3));
        }
    }

    #pragma unroll
    for (int nt = 0; nt < 16; nt++)
        acc[nt][0] = acc[nt][1] = acc[nt][2] = acc[nt][3] = 0.f;
    #pragma unroll
    for (int ks = 0; ks < 8; ks++) {
        #pragma unroll
        for (int nt = 0; nt < 16; nt += 2) {
            uint32_t bh[4], bl[4];
            ldsm_x4(bPr + 2 * WIMG + nt * (8 * WST * 2) + ks * 32, bh);
            ldsm_x4(bPr + 3 * WIMG + nt * (8 * WST * 2) + ks * 32, bl);
            mma16816(acc[nt], a2h[ks], bh); mma16816(acc[nt + 1], a2h[ks], bh + 2);
            mma16816(acc[nt], a2h[ks], bl); mma16816(acc[nt + 1], a2h[ks], bl + 2);
            mma16816(acc[nt], a2l[ks], bh); mma16816(acc[nt + 1], a2l[ks], bh + 2);
        }
    }

    float* sxf = (float*)sdyn;
    const int g = lane >> 2;
    #pragma unroll
    for (int nt = 0; nt < 16; nt++) {
        const int nc = nt * 8 + c2;
        const float b0 = s_bias2[nc], b1 = s_bias2[nc + 1];
        *(float2*)(&sxf[(m0 + g) * SXF_STRIDE + nc])     = make_float2(acc[nt][0] + b0, acc[nt][1] + b1);
        *(float2*)(&sxf[(m0 + g + 8) * SXF_STRIDE + nc]) = make_float2(acc[nt][2] + b0, acc[nt][3] + b1);
    }
    __syncthreads();

    {
        float4* xo = (float4*)(g_xembed + (size_t)row0 * 128);
        #pragma unroll
        for (int i = 0; i < 16; i++) {
            int idx = t + i * 256;
            int row = idx >> 5;
            int c4  = (idx & 31) * 4;
            const float* p = &sxf[row * SXF_STRIDE + c4];
            xo[idx] = make_float4(p[0], p[1], p[2], p[3]);
        }
    }
    if (t < 128) {
        float s = 0.f;
        for (int r = 0; r < 128; r++)
            if (s_vf[r]) s += __expf(sxf[r * SXF_STRIDE + t]);
        if (s != 0.f) atomicAdd(&g_sumexp[b * 128 + t], s);
    }
}

// ---------------------------------------------------------------------------
// Kernel 2 (HMMA, R8 base + in-register axi frags + copy overlap):
// out = relu([a*relu(xf@We), xf]@Wo1+bo1)@Wo2+bo2
// ---------------------------------------------------------------------------
#define XFHI 0
#define XFLO 34816
#define WO1HI 69632             // 67584 bytes (128 n-rows x 264 k-stride x 2B)
#define WO1LO 137216            // 67584 bytes (overlays WE after stage A)
#define WEHI 139264
#define WELO 174080
#define DSMEM_OUT 208896

// copy one Wo1 half-image into a 264-stride smem buffer; partial=true copies
// only the k in [128,256) rows (xf part) when no valid rows exist in the CTA.
static __device__ __forceinline__ void copy_wo1_half(
    unsigned char* sm, uint32_t dst0, int img, int half, int t, bool full)
{
    const uint4* src = (const uint4*)(g_wo1T[img] + (half * 128) * 256);
    if (full) {
        #pragma unroll
        for (int i = 0; i < 16; i++) {
            int e = t + i * 256;
            int r = e >> 5;
            int kq = (e & 31) * 8;
            *(uint4*)(sm + dst0 + ((r * 264 + kq) << 1)) = src[e];
        }
    } else {
        #pragma unroll
        for (int i = 0; i < 8; i++) {
            int e = t + i * 256;
            int r = e >> 4;
            int kq = 128 + (e & 15) * 8;
            *(uint4*)(sm + dst0 + ((r * 264 + kq) << 1)) = src[r * 32 + (kq >> 3)];
        }
    }
}

__global__ __launch_bounds__(256, 1) void k_out_hmma(
    const float* __restrict__ bo1,
    const float* __restrict__ Wo2, const float* __restrict__ bo2,
    float* __restrict__ out)
{
    __shared__ float s_bo1[256], s_wo2[256], s_inv[128];
    __shared__ unsigned char s_vf[128];

    const int t    = threadIdx.x;
    const int lane = t & 31;
    const int w    = t >> 5;
    const int row0 = blockIdx.x * 128;
    const int b    = row0 / NC;
    const uint32_t sbase = smem_u32(sdyn);

    if (t < 128) {
        s_inv[t] = 1.0f / g_sumexp[b * 128 + t];
        const int lenb = g_len[b];
        const int rem = row0 + t - b * NC;
        const int i  = rem / 1600;
        const int j  = (rem / 40) % 40;
        const int kk = rem % 40;
        s_vf[t] = (i < j) && (j < kk) && (kk < lenb);
    }
    s_bo1[t] = bo1[t];
    s_wo2[t] = Wo2[t];
    const int bany = __syncthreads_or((t < 128) ? (int)s_vf[t] : 0);

    // xf tile -> bf16 hi/lo images
    {
        const float4* xg = (const float4*)(g_xembed + (size_t)row0 * 128);
        #pragma unroll
        for (int i = 0; i < 16; i++) {
            int fidx = t + i * 256;
            float4 v = xg[fidx];
            int row = fidx >> 5;
            int k   = (fidx & 31) * 4;
            uint32_t hA = pack_bf2(v.x, v.y);
            uint32_t hB = pack_bf2(v.z, v.w);
            uint32_t lA = pack_bf2(v.x - bfhi(v.x), v.y - bfhi(v.y));
            uint32_t lB = pack_bf2(v.z - bfhi(v.z), v.w - bfhi(v.w));
            size_t off = ((size_t)row * WST + k) * 2;
            *(u64*)(sdyn + XFHI + off) = ((u64)hB << 32) | hA;
            *(u64*)(sdyn + XFLO + off) = ((u64)lB << 32) | lA;
        }
    }
    // We images (stage A operand) — only when CTA has valid rows
    if (bany) {
        const float4* ws = (const float4*)g_weT;
        float4* wd = (float4*)(sdyn + WEHI);
        #pragma unroll
        for (int i = 0; i < 17; i++) wd[t + i * 256] = ws[t + i * 256];
    }
    // pre-copy Wo1 half0 HI image (region unused until stage B)
    copy_wo1_half(sdyn, WO1HI, 0, 0, t, bany != 0);
    __syncthreads();

    const int m0 = w * 16;
    const int c2 = (lane & 3) * 2;
    const int g  = lane >> 2;
    const uint32_t aAddr = sbase + (((m0 + (lane & 15)) * WST + (lane >> 4) * 8) << 1);
    const uint32_t bPr136 = sbase +
        (((((lane & 7) + ((lane >> 4) << 3)) * WST) + ((lane >> 3) & 1) * 8) << 1);

    const int vlane = s_vf[m0 + (lane & 15)];
    const int warp_any = __any_sync(0xffffffffu, vlane);

    // ---- stage A: axi = a .* relu(xf @ We); frags built IN REGISTERS ----
    uint32_t axh[8][4], axl[8][4];
    if (warp_any) {
        const int r0 = m0 + g, r1 = r0 + 8;
        const bool v0 = s_vf[r0], v1 = s_vf[r1];
        #pragma unroll
        for (int ntg = 0; ntg < 16; ntg += 4) {
            float acc[4][4];
            #pragma unroll
            for (int q = 0; q < 4; q++)
                acc[q][0] = acc[q][1] = acc[q][2] = acc[q][3] = 0.f;
            #pragma unroll
            for (int ks = 0; ks < 8; ks++) {
                uint32_t ah[4], al[4];
                ldsm_x4(aAddr + XFHI + ks * 32, ah);
                ldsm_x4(aAddr + XFLO + ks * 32, al);
                uint32_t bhA[4], bhB[4], blA[4], blB[4];
                ldsm_x4(bPr136 + WEHI + (ntg + 0) * (8 * WST * 2) + ks * 32, bhA);
                ldsm_x4(bPr136 + WEHI + (ntg + 2) * (8 * WST * 2) + ks * 32, bhB);
                ldsm_x4(bPr136 + WELO + (ntg + 0) * (8 * WST * 2) + ks * 32, blA);
                ldsm_x4(bPr136 + WELO + (ntg + 2) * (8 * WST * 2) + ks * 32, blB);
                mma16816(acc[0], ah, bhA);     mma16816(acc[1], ah, bhA + 2);
                mma16816(acc[2], ah, bhB);     mma16816(acc[3], ah, bhB + 2);
                mma16816(acc[0], ah, blA);     mma16816(acc[1], ah, blA + 2);
                mma16816(acc[2], ah, blB);     mma16816(acc[3], ah, blB + 2);
                mma16816(acc[0], al, bhA);     mma16816(acc[1], al, bhA + 2);
                mma16816(acc[2], al, bhB);     mma16816(acc[3], al, bhB + 2);
            }
            // epilogue -> A-fragments for cols [ntg*8, ntg*8+32)
            #pragma unroll
            for (int q = 0; q < 4; q++) {
                const int nt = ntg + q;
                const int c = nt * 8 + c2;
                const float i0 = s_inv[c], i1 = s_inv[c + 1];
                float v00 = 0.f, v01 = 0.f, v10 = 0.f, v11 = 0.f;
                if (v0) {
                    __nv_bfloat162 h = *(__nv_bfloat162*)(sdyn + XFHI + ((r0 * WST + c) << 1));
                    __nv_bfloat162 l = *(__nv_bfloat162*)(sdyn + XFLO + ((r0 * WST + c) << 1));
                    float x0 = __bfloat162float(h.x) + __bfloat162float(l.x);
                    float x1 = __bfloat162float(h.y) + __bfloat162float(l.y);
                    v00 = __expf(x0) * i0 * fmaxf(acc[q][0], 0.f);
                    v01 = __expf(x1) * i1 * fmaxf(acc[q][1], 0.f);
                }
                if (v1) {
                    __nv_bfloat162 h = *(__nv_bfloat162*)(sdyn + XFHI + ((r1 * WST + c) << 1));
                    __nv_bfloat162 l = *(__nv_bfloat162*)(sdyn + XFLO + ((r1 * WST + c) << 1));
                    float x0 = __bfloat162float(h.x) + __bfloat162float(l.x);
                    float x1 = __bfloat162float(h.y) + __bfloat162float(l.y);
                    v10 = __expf(x0) * i0 * fmaxf(acc[q][2], 0.f);
                    v11 = __expf(x1) * i1 * fmaxf(acc[q][3], 0.f);
                }
                const int kst = nt >> 1;          // A-frag k-step
                const int h2  = (nt & 1) * 2;     // 0: k 0-7, 2: k 8-15
                axh[kst][0 + h2] = pack_bf2(v00, v01);
                axh[kst][1 + h2] = pack_bf2(v10, v11);
                axl[kst][0 + h2] = pack_bf2(v00 - bfhi(v00), v01 - bfhi(v01));
                axl[kst][1 + h2] = pack_bf2(v10 - bfhi(v10), v11 - bfhi(v11));
            }
        }
    }
    __syncthreads();          // stage A done: WE region dead

    // copy Wo1 half0 LO image (overlays WE)
    copy_wo1_half(sdyn, WO1LO, 1, 0, t, bany != 0);
    __syncthreads();

    // ---- stage B: two 128-col halves of Wo1 ----
    float rsum0 = 0.f, rsum1 = 0.f;
    const uint32_t bPr264 = sbase +
        (((((lane & 7) + ((lane >> 4) << 3)) * 264) + ((lane >> 3) & 1) * 8) << 1);

    #pragma unroll
    for (int half = 0; half < 2; half++) {
        if (half == 1) {
            __syncthreads();   // half0 reads complete
            copy_wo1_half(sdyn, WO1HI, 0, 1, t, bany != 0);
            copy_wo1_half(sdyn, WO1LO, 1, 1, t, bany != 0);
            __syncthreads();
        }
        #pragma unroll
        for (int ntg = 0; ntg < 16; ntg += 4) {
            float acc[4][4];
            #pragma unroll
            for (int q = 0; q < 4; q++)
                acc[q][0] = acc[q][1] = acc[q][2] = acc[q][3] = 0.f;
            #pragma unroll
            for (int ks = 0; ks < 8; ks++) {
                uint32_t ah[4], al[4];
                ldsm_x4(aAddr + XFHI + ks * 32, ah);
                ldsm_x4(aAddr + XFLO + ks * 32, al);
                // xf part: Wo1 rows k = 128 + ks*16
                {
                    uint32_t bhA[4], bhB[4], blA[4], blB[4];
                    const uint32_t ko = (128 + ks * 16) * 2;
                    ldsm_x4(bPr264 + WO1HI + (ntg + 0) * (8 * 264 * 2) + ko, bhA);
                    ldsm_x4(bPr264 + WO1HI + (ntg + 2) * (8 * 264 * 2) + ko, bhB);
                    ldsm_x4(bPr264 + WO1LO + (ntg + 0) * (8 * 264 * 2) + ko, blA);
                    ldsm_x4(bPr264 + WO1LO + (ntg + 2) * (8 * 264 * 2) + ko, blB);
                    mma16816(acc[0], ah, bhA);  mma16816(acc[1], ah, bhA + 2);
                    mma16816(acc[2], ah, bhB);  mma16816(acc[3], ah, bhB + 2);
                    mma16816(acc[0], ah, blA);  mma16816(acc[1], ah, blA + 2);
                    mma16816(acc[2], ah, blB);  mma16816(acc[3], ah, blB + 2);
                    mma16816(acc[0], al, bhA);  mma16816(acc[1], al, bhA + 2);
                    mma16816(acc[2], al, bhB);  mma16816(acc[3], al, bhB + 2);
                }
                // a*x_inner part: Wo1 rows k = ks*16 (warp-uniform skip), A from regs
                if (warp_any) {
                    uint32_t bhA[4], bhB[4], blA[4], blB[4];
                    const uint32_t ko = (ks * 16) * 2;
                    ldsm_x4(bPr264 + WO1HI + (ntg + 0) * (8 * 264 * 2) + ko, bhA);
                    ldsm_x4(bPr264 + WO1HI + (ntg + 2) * (8 * 264 * 2) + ko, bhB);
                    ldsm_x4(bPr264 + WO1LO + (ntg + 0) * (8 * 264 * 2) + ko, blA);
                    ldsm_x4(bPr264 + WO1LO + (ntg + 2) * (8 * 264 * 2) + ko, blB);
                    mma16816(acc[0], axh[ks], bhA);  mma16816(acc[1], axh[ks], bhA + 2);
                    mma16816(acc[2], axh[ks], bhB);  mma16816(acc[3], axh[ks], bhB + 2);
                    mma16816(acc[0], axh[ks], blA);  mma16816(acc[1], axh[ks], blA + 2);
                    mma16816(acc[2], axh[ks], blB);  mma16816(acc[3], axh[ks], blB + 2);
                    mma16816(acc[0], axl[ks], bhA);  mma16816(acc[1], axl[ks], bhA + 2);
                    mma16816(acc[2], axl[ks], bhB);  mma16816(acc[3], axl[ks], bhB + 2);
                }
            }
            #pragma unroll
            for (int q = 0; q < 4; q++) {
                const int col = half * 128 + (ntg + q) * 8 + c2;
                const float g0 = fmaxf(acc[q][0] + s_bo1[col],     0.f);
                const float g1 = fmaxf(acc[q][1] + s_bo1[col + 1], 0.f);
                const float g2 = fmaxf(acc[q][2] + s_bo1[col],     0.f);
                const float g3 = fmaxf(acc[q][3] + s_bo1[col + 1], 0.f);
                rsum0 += g0 * s_wo2[col] + g1 * s_wo2[col + 1];
                rsum1 += g2 * s_wo2[col] + g3 * s_wo2[col + 1];
            }
        }
    }

    rsum0 += __shfl_xor_sync(0xffffffffu, rsum0, 1);
    rsum0 += __shfl_xor_sync(0xffffffffu, rsum0, 2);
    rsum1 += __shfl_xor_sync(0xffffffffu, rsum1, 1);
    rsum1 += __shfl_xor_sync(0xffffffffu, rsum1, 2);
    if ((lane & 3) == 0) {
        const float b2 = bo2[0];
        out[row0 + m0 + g]     = rsum0 + b2;
        out[row0 + m0 + g + 8] = rsum1 + b2;
    }
}

// ---------------------------------------------------------------------------
extern "C" void kernel_launch(void* const* d_in, const int* in_sizes, int n_in,
                              void* d_out, int out_size) {
    const float* x          = (const float*)d_in[0];
    const unsigned char* mk = (const unsigned char*)d_in[1];
    const float* Wi1        = (const float*)d_in[2];
    const float* bi1        = (const float*)d_in[3];
    const float* Wi2        = (const float*)d_in[4];
    const float* bi2        = (const float*)d_in[5];
    const float* We         = (const float*)d_in[6];
    const float* Wo1        = (const float*)d_in[7];
    const float* bo1        = (const float*)d_in[8];
    const float* Wo2        = (const float*)d_in[9];
    const float* bo2        = (const float*)d_in[10];
    float* out              = (float*)d_out;

    cudaFuncSetAttribute(k_embed_hmma, cudaFuncAttributeMaxDynamicSharedMemorySize, DSMEM);
    cudaFuncSetAttribute(k_out_hmma, cudaFuncAttributeMaxDynamicSharedMemorySize, DSMEM_OUT);

    const int prep_elems = 6 * 128 * WST + 2 * 65536;
    k_setup<<<1, 512>>>(mk);
    k_prep<<<(prep_elems + 255) / 256, 256>>>(Wi1, Wi2, We, Wo1);
    k_embed_hmma<<<RT / 128, 256, DSMEM>>>(x, bi1, bi2);
    k_out_hmma<<<RT / 128, 256, DSMEM_OUT>>>(bo1, Wo2, bo2, out);
}

// round 12
// speedup vs baseline: 1.5874x; 1.0092x over previous
#include <cuda_runtime.h>
#include <cuda_bf16.h>
#include <cstdint>

#define B_   4
#define N_   40
#define NC   64000      // 40^3
#define RT   256000     // B * N^3
#define WST  136

typedef unsigned long long u64;

// ---------------- scratch (device globals per allocation rules) ------------
__device__ float g_xembed[(size_t)RT * 128];
__device__ float g_sumexp[B_ * 128];
__device__ int   g_len[B_];
__device__ __align__(16) unsigned short g_wT[4][128 * WST];     // Wi1/Wi2 hi,lo [n][k]
__device__ __align__(16) unsigned short g_weT[2][128 * WST];    // We hi,lo [n][k]
__device__ __align__(16) unsigned short g_wo1T[2][256 * 256];   // Wo1 hi,lo [n][k]

// ---------------- helpers ---------------------------------------------------
static __device__ __forceinline__ uint32_t smem_u32(const void* p) {
    uint32_t a;
    asm("{ .reg .u64 t; cvta.to.shared.u64 t, %1; cvt.u32.u64 %0, t; }" : "=r"(a) : "l"(p));
    return a;
}
static __device__ __forceinline__ float bfhi(float f) {
    return __bfloat162float(__float2bfloat16(f));
}
static __device__ __forceinline__ uint32_t pack_bf2(float lo, float hi) {
    __nv_bfloat162 h = __floats2bfloat162_rn(lo, hi);
    return *reinterpret_cast<uint32_t*>(&h);
}
static __device__ __forceinline__ void ldsm_x4(uint32_t a, uint32_t* r) {
    asm volatile("ldmatrix.sync.aligned.m8n8.x4.shared.b16 {%0,%1,%2,%3}, [%4];"
        : "=r"(r[0]), "=r"(r[1]), "=r"(r[2]), "=r"(r[3]) : "r"(a));
}
static __device__ __forceinline__ void mma16816(float* d, const uint32_t* a, const uint32_t* b) {
    asm volatile("mma.sync.aligned.m16n8k16.row.col.f32.bf16.bf16.f32 "
        "{%0,%1,%2,%3}, {%4,%5,%6,%7}, {%8,%9}, {%0,%1,%2,%3};"
        : "+f"(d[0]), "+f"(d[1]), "+f"(d[2]), "+f"(d[3])
        : "r"(a[0]), "r"(a[1]), "r"(a[2]), "r"(a[3]), "r"(b[0]), "r"(b[1]));
}

// ---------------------------------------------------------------------------
// Kernel 0a: mask -> lengths, zero softmax denominators.
// ---------------------------------------------------------------------------
__global__ void k_setup(const unsigned char* __restrict__ mraw) {
    int t = threadIdx.x;
    if (t < B_ * 128) g_sumexp[t] = 0.f;
    if (t < B_) {
        int cnt = 0;
        if (mraw[1] != 0) {
            for (int j = 0; j < N_; j++) cnt += (mraw[t * N_ + j] != 0) ? 1 : 0;
        } else {
            const unsigned int* mi = (const unsigned int*)mraw;
            for (int j = 0; j < N_; j++) cnt += (mi[t * N_ + j] != 0u) ? 1 : 0;
        }
        g_len[t] = cnt;
    }
}

// ---------------------------------------------------------------------------
// Kernel 0b: transposed bf16 hi/lo weight images for Wi1, Wi2, We, Wo1.
// ---------------------------------------------------------------------------
__global__ void k_prep(const float* __restrict__ Wi1, const float* __restrict__ Wi2,
                       const float* __restrict__ We,  const float* __restrict__ Wo1) {
    int idx = blockIdx.x * 256 + threadIdx.x;
    if (idx < 4 * 128 * WST) {
        int mat = idx / (128 * WST);
        int r   = idx % (128 * WST);
        int n   = r / WST;
        int k   = r % WST;
        float v = 0.f;
        if (k < 128) {
            v = (mat < 2 ? Wi1 : Wi2)[k * 128 + n];
            if (mat & 1) v = v - bfhi(v);
        }
        __nv_bfloat16 h = __float2bfloat16(v);
        g_wT[mat][n * WST + k] = *reinterpret_cast<unsigned short*>(&h);
    } else if (idx < 6 * 128 * WST) {
        int r   = idx - 4 * 128 * WST;
        int img = r / (128 * WST);
        int rr  = r % (128 * WST);
        int n   = rr / WST;
        int k   = rr % WST;
        float v = 0.f;
        if (k < 128) {
            v = We[k * 128 + n];
            if (img) v = v - bfhi(v);
        }
        __nv_bfloat16 h = __float2bfloat16(v);
        g_weT[img][n * WST + k] = *reinterpret_cast<unsigned short*>(&h);
    } else if (idx < 6 * 128 * WST + 2 * 65536) {
        int r   = idx - 6 * 128 * WST;
        int img = r / 65536;
        int rr  = r % 65536;
        int n   = rr / 256;
        int k   = rr % 256;
        float v = Wo1[k * 256 + n];
        if (img) v = v - bfhi(v);
        __nv_bfloat16 h = __float2bfloat16(v);
        g_wo1T[img][n * 256 + k] = *reinterpret_cast<unsigned short*>(&h);
    }
}

// ---------------------------------------------------------------------------
// Kernel 1 (HMMA, unchanged from round-8 best): x_embed + sumexp.
// ---------------------------------------------------------------------------
#define AHI_OFF 0
#define ALO_OFF 34816
#define W_OFF   69632
#define WIMG    34816
#define SXF_STRIDE 132
#define DSMEM   208896

extern __shared__ unsigned char sdyn[];
__global__ __launch_bounds__(256, 1) void k_embed_hmma(
    const float* __restrict__ x,
    const float* __restrict__ bi1, const float* __restrict__ bi2)
{
    __shared__ float s_bias1[128], s_bias2[128];
    __shared__ unsigned char s_vf[128];

    const int t    = threadIdx.x;
    const int lane = t & 31;
    const int w    = t >> 5;
    const int row0 = blockIdx.x * 128;
    const int b    = row0 / NC;
    const uint32_t sbase = smem_u32(sdyn);

    {
        const float4* ws = (const float4*)g_wT;
        float4* wd = (float4*)(sdyn + W_OFF);
        #pragma unroll
        for (int i = 0; i < 34; i++) wd[t + i * 256] = ws[t + i * 256];
    }
    {
        const float4* xg = (const float4*)(x + (size_t)row0 * 128);
        #pragma unroll
        for (int i = 0; i < 16; i++) {
            int fidx = t + i * 256;
            float4 v = xg[fidx];
            int row = fidx >> 5;
            int k   = (fidx & 31) * 4;
            uint32_t hA = pack_bf2(v.x, v.y);
            uint32_t hB = pack_bf2(v.z, v.w);
            uint32_t lA = pack_bf2(v.x - bfhi(v.x), v.y - bfhi(v.y));
            uint32_t lB = pack_bf2(v.z - bfhi(v.z), v.w - bfhi(v.w));
            size_t off = ((size_t)row * WST + k) * 2;
            *(u64*)(sdyn + AHI_OFF + off) = ((u64)hB << 32) | hA;
            *(u64*)(sdyn + ALO_OFF + off) = ((u64)lB << 32) | lA;
        }
    }
    if (t < 128) {
        s_bias1[t] = bi1[t];
        s_bias2[t] = bi2[t];
        const int lenb = g_len[b];
        const int rem = row0 + t - b * NC;
        const int i  = rem / 1600;
        const int j  = (rem / 40) % 40;
        const int kk = rem % 40;
        s_vf[t] = (i < j) && (j < kk) && (kk < lenb);
    }
    __syncthreads();

    const int m0 = w * 16;
    const int c2 = (lane & 3) * 2;
    const uint32_t aHi = sbase + AHI_OFF + (((m0 + (lane & 15)) * WST + (lane >> 4) * 8) << 1);
    const uint32_t aLo = aHi + (ALO_OFF - AHI_OFF);
    const uint32_t bPr = sbase + W_OFF +
        (((((lane & 7) + ((lane >> 4) << 3)) * WST) + ((lane >> 3) & 1) * 8) << 1);

    float acc[16][4];
    #pragma unroll
    for (int nt = 0; nt < 16; nt++)
        acc[nt][0] = acc[nt][1] = acc[nt][2] = acc[nt][3] = 0.f;

    #pragma unroll
    for (int ks = 0; ks < 8; ks++) {
        uint32_t ahi[4], alo[4];
        ldsm_x4(aHi + ks * 32, ahi);
        ldsm_x4(aLo + ks * 32, alo);
        #pragma unroll
        for (int nt = 0; nt < 16; nt += 2) {
            uint32_t bh[4], bl[4];
            ldsm_x4(bPr + 0 * WIMG + nt * (8 * WST * 2) + ks * 32, bh);
            ldsm_x4(bPr + 1 * WIMG + nt * (8 * WST * 2) + ks * 32, bl);
            mma16816(acc[nt], ahi, bh);     mma16816(acc[nt + 1], ahi, bh + 2);
            mma16816(acc[nt], ahi, bl);     mma16816(acc[nt + 1], ahi, bl + 2);
            mma16816(acc[nt], alo, bh);     mma16816(acc[nt + 1], alo, bh + 2);
        }
    }
    __syncthreads();

    uint32_t a2h[8][4], a2l[8][4];
    #pragma unroll
    for (int ks = 0; ks < 8; ks++) {
        #pragma unroll
        for (int h = 0; h < 2; h++) {
            const int nt = 2 * ks + h;
            const float b0 = s_bias1[nt * 8 + c2];
            const float b1 = s_bias1[nt * 8 + c2 + 1];
            float f0 = fmaxf(acc[nt][0] + b0, 0.f);
            float f1 = fmaxf(acc[nt][1] + b1, 0.f);
            float f2 = fmaxf(acc[nt][2] + b0, 0.f);
            float f3 = fmaxf(acc[nt][3] + b1, 0.f);
            a2h[ks][0 + 2 * h] = pack_bf2(f0, f1);
            a2h[ks][1 + 2 * h] = pack_bf2(f2, f3);
            a2l[ks][0 + 2 * h] = pack_bf2(f0 - bfhi(f0), f1 - bfhi(f1));
            a2l[ks][1 + 2 * h] = pack_bf2(f2 - bfhi(f2), f3 - bfhi(f3));
        }
    }

    #pragma unroll
    for (int nt = 0; nt < 16; nt++)
        acc[nt][0] = acc[nt][1] = acc[nt][2] = acc[nt][3] = 0.f;
    #pragma unroll
    for (int ks = 0; ks < 8; ks++) {
        #pragma unroll
        for (int nt = 0; nt < 16; nt += 2) {
            uint32_t bh[4], bl[4];
            ldsm_x4(bPr + 2 * WIMG + nt * (8 * WST * 2) + ks * 32, bh);
            ldsm_x4(bPr + 3 * WIMG + nt * (8 * WST * 2) + ks * 32, bl);
            mma16816(acc[nt], a2h[ks], bh); mma16816(acc[nt + 1], a2h[ks], bh + 2);
            mma16816(acc[nt], a2h[ks], bl); mma16816(acc[nt + 1], a2h[ks], bl + 2);
            mma16816(acc[nt], a2l[ks], bh); mma16816(acc[nt + 1], a2l[ks], bh + 2);
        }
    }

    float* sxf = (float*)sdyn;
    const int g = lane >> 2;
    #pragma unroll
    for (int nt = 0; nt < 16; nt++) {
        const int nc = nt * 8 + c2;
        const float b0 = s_bias2[nc], b1 = s_bias2[nc + 1];
        *(float2*)(&sxf[(m0 + g) * SXF_STRIDE + nc])     = make_float2(acc[nt][0] + b0, acc[nt][1] + b1);
        *(float2*)(&sxf[(m0 + g + 8) * SXF_STRIDE + nc]) = make_float2(acc[nt][2] + b0, acc[nt][3] + b1);
    }
    __syncthreads();

    {
        float4* xo = (float4*)(g_xembed + (size_t)row0 * 128);
        #pragma unroll
        for (int i = 0; i < 16; i++) {
            int idx = t + i * 256;
            int row = idx >> 5;
            int c4  = (idx & 31) * 4;
            const float* p = &sxf[row * SXF_STRIDE + c4];
            xo[idx] = make_float4(p[0], p[1], p[2], p[3]);
        }
    }
    if (t < 128) {
        float s = 0.f;
        for (int r = 0; r < 128; r++)
            if (s_vf[r]) s += __expf(sxf[r * SXF_STRIDE + t]);
        if (s != 0.f) atomicAdd(&g_sumexp[b * 128 + t], s);
    }
}

// ---------------------------------------------------------------------------
// Kernel 2 (HMMA): out = relu([a*relu(xf@We), xf]@Wo1+bo1)@Wo2+bo2
// Precision-split only on the dominant xf@Wo1 path (bf16x3); the small paths
// (xf@We and axi@Wo1_top, both scaled by a ~ 1e-3) run plain bf16 — their
// 2^-9 relative error contributes < 1e-6 to the output.
// ---------------------------------------------------------------------------
#define XFHI 0
#define XFLO 34816
#define WO1HI 69632             // 67584 bytes (128 n-rows x 264 k-stride x 2B)
#define WO1LO 137216            // 67584 bytes
#define WEHI 139264             // overlaid by WO1LO after stage A
#define DSMEM_OUT 204800

// copy one Wo1 half-image into a 264-stride smem buffer; full=false copies
// only the k in [128,256) rows (xf part) when no valid rows exist in the CTA.
static __device__ __forceinline__ void copy_wo1_half(
    unsigned char* sm, uint32_t dst0, int img, int half, int t, bool full)
{
    const uint4* src = (const uint4*)(g_wo1T[img] + (half * 128) * 256);
    if (full) {
        #pragma unroll
        for (int i = 0; i < 16; i++) {
            int e = t + i * 256;
            int r = e >> 5;
            int kq = (e & 31) * 8;
            *(uint4*)(sm + dst0 + ((r * 264 + kq) << 1)) = src[e];
        }
    } else {
        #pragma unroll
        for (int i = 0; i < 8; i++) {
            int e = t + i * 256;
            int r = e >> 4;
            int kq = 128 + (e & 15) * 8;
            *(uint4*)(sm + dst0 + ((r * 264 + kq) << 1)) = src[r * 32 + (kq >> 3)];
        }
    }
}

__global__ __launch_bounds__(256, 1) void k_out_hmma(
    const float* __restrict__ bo1,
    const float* __restrict__ Wo2, const float* __restrict__ bo2,
    float* __restrict__ out)
{
    __shared__ float s_bo1[256], s_wo2[256], s_inv[128];
    __shared__ unsigned char s_vf[128];

    const int t    = threadIdx.x;
    const int lane = t & 31;
    const int w    = t >> 5;
    const int row0 = blockIdx.x * 128;
    const int b    = row0 / NC;
    const uint32_t sbase = smem_u32(sdyn);

    if (t < 128) {
        s_inv[t] = 1.0f / g_sumexp[b * 128 + t];
        const int lenb = g_len[b];
        const int rem = row0 + t - b * NC;
        const int i  = rem / 1600;
        const int j  = (rem / 40) % 40;
        const int kk = rem % 40;
        s_vf[t] = (i < j) && (j < kk) && (kk < lenb);
    }
    s_bo1[t] = bo1[t];
    s_wo2[t] = Wo2[t];
    const int bany = __syncthreads_or((t < 128) ? (int)s_vf[t] : 0);

    // xf tile -> bf16 hi/lo images
    {
        const float4* xg = (const float4*)(g_xembed + (size_t)row0 * 128);
        #pragma unroll
        for (int i = 0; i < 16; i++) {
            int fidx = t + i * 256;
            float4 v = xg[fidx];
            int row = fidx >> 5;
            int k   = (fidx & 31) * 4;
            uint32_t hA = pack_bf2(v.x, v.y);
            uint32_t hB = pack_bf2(v.z, v.w);
            uint32_t lA = pack_bf2(v.x - bfhi(v.x), v.y - bfhi(v.y));
            uint32_t lB = pack_bf2(v.z - bfhi(v.z), v.w - bfhi(v.w));
            size_t off = ((size_t)row * WST + k) * 2;
            *(u64*)(sdyn + XFHI + off) = ((u64)hB << 32) | hA;
            *(u64*)(sdyn + XFLO + off) = ((u64)lB << 32) | lA;
        }
    }
    // We hi image only (stage A runs plain bf16) — only when CTA has valid rows
    if (bany) {
        const float4* ws = (const float4*)g_weT[0];
        float4* wd = (float4*)(sdyn + WEHI);
        #pragma unroll
        for (int i = 0; i < 9; i++) {
            int e = t + i * 256;
            if (e < 2176) wd[e] = ws[e];
        }
    }
    // pre-copy Wo1 half0 HI image (region unused until stage B)
    copy_wo1_half(sdyn, WO1HI, 0, 0, t, bany != 0);
    __syncthreads();

    const int m0 = w * 16;
    const int c2 = (lane & 3) * 2;
    const int g  = lane >> 2;
    const uint32_t aAddr = sbase + (((m0 + (lane & 15)) * WST + (lane >> 4) * 8) << 1);
    const uint32_t bPr136 = sbase +
        (((((lane & 7) + ((lane >> 4) << 3)) * WST) + ((lane >> 3) & 1) * 8) << 1);

    const int vlane = s_vf[m0 + (lane & 15)];
    const int warp_any = __any_sync(0xffffffffu, vlane);

    // ---- stage A (plain bf16): axi = a .* relu(xf @ We); frags in registers ----
    uint32_t axh[8][4];
    if (warp_any) {
        const int r0 = m0 + g, r1 = r0 + 8;
        const bool v0 = s_vf[r0], v1 = s_vf[r1];
        #pragma unroll
        for (int ntg = 0; ntg < 16; ntg += 4) {
            float acc[4][4];
            #pragma unroll
            for (int q = 0; q < 4; q++)
                acc[q][0] = acc[q][1] = acc[q][2] = acc[q][3] = 0.f;
            #pragma unroll
            for (int ks = 0; ks < 8; ks++) {
                uint32_t ah[4];
                ldsm_x4(aAddr + XFHI + ks * 32, ah);
                uint32_t bhA[4], bhB[4];
                ldsm_x4(bPr136 + WEHI + (ntg + 0) * (8 * WST * 2) + ks * 32, bhA);
                ldsm_x4(bPr136 + WEHI + (ntg + 2) * (8 * WST * 2) + ks * 32, bhB);
                mma16816(acc[0], ah, bhA);     mma16816(acc[1], ah, bhA + 2);
                mma16816(acc[2], ah, bhB);     mma16816(acc[3], ah, bhB + 2);
            }
            // epilogue -> bf16 A-fragments for cols [ntg*8, ntg*8+32)
            #pragma unroll
            for (int q = 0; q < 4; q++) {
                const int nt = ntg + q;
                const int c = nt * 8 + c2;
                const float i0 = s_inv[c], i1 = s_inv[c + 1];
                float v00 = 0.f, v01 = 0.f, v10 = 0.f, v11 = 0.f;
                if (v0) {
                    __nv_bfloat162 h = *(__nv_bfloat162*)(sdyn + XFHI + ((r0 * WST + c) << 1));
                    __nv_bfloat162 l = *(__nv_bfloat162*)(sdyn + XFLO + ((r0 * WST + c) << 1));
                    float x0 = __bfloat162float(h.x) + __bfloat162float(l.x);
                    float x1 = __bfloat162float(h.y) + __bfloat162float(l.y);
                    v00 = __expf(x0) * i0 * fmaxf(acc[q][0], 0.f);
                    v01 = __expf(x1) * i1 * fmaxf(acc[q][1], 0.f);
                }
                if (v1) {
                    __nv_bfloat162 h = *(__nv_bfloat162*)(sdyn + XFHI + ((r1 * WST + c) << 1));
                    __nv_bfloat162 l = *(__nv_bfloat162*)(sdyn + XFLO + ((r1 * WST + c) << 1));
                    float x0 = __bfloat162float(h.x) + __bfloat162float(l.x);
                    float x1 = __bfloat162float(h.y) + __bfloat162float(l.y);
                    v10 = __expf(x0) * i0 * fmaxf(acc[q][2], 0.f);
                    v11 = __expf(x1) * i1 * fmaxf(acc[q][3], 0.f);
                }
                const int kst = nt >> 1;          // A-frag k-step
                const int h2  = (nt & 1) * 2;     // 0: k 0-7, 2: k 8-15
                axh[kst][0 + h2] = pack_bf2(v00, v01);
                axh[kst][1 + h2] = pack_bf2(v10, v11);
            }
        }
    }
    __syncthreads();          // stage A done: WE region dead

    // copy Wo1 half0 LO image (overlays WE)
    copy_wo1_half(sdyn, WO1LO, 1, 0, t, bany != 0);
    __syncthreads();

    // ---- stage B: two 128-col halves of Wo1 ----
    float rsum0 = 0.f, rsum1 = 0.f;
    const uint32_t bPr264 = sbase +
        (((((lane & 7) + ((lane >> 4) << 3)) * 264) + ((lane >> 3) & 1) * 8) << 1);

    #pragma unroll
    for (int half = 0; half < 2; half++) {
        if (half == 1) {
            __syncthreads();   // half0 reads complete
            copy_wo1_half(sdyn, WO1HI, 0, 1, t, bany != 0);
            copy_wo1_half(sdyn, WO1LO, 1, 1, t, bany != 0);
            __syncthreads();
        }
        #pragma unroll
        for (int ntg = 0; ntg < 16; ntg += 4) {
            float acc[4][4];
            #pragma unroll
            for (int q = 0; q < 4; q++)
                acc[q][0] = acc[q][1] = acc[q][2] = acc[q][3] = 0.f;
            #pragma unroll
            for (int ks = 0; ks < 8; ks++) {
                uint32_t ah[4], al[4];
                ldsm_x4(aAddr + XFHI + ks * 32, ah);
                ldsm_x4(aAddr + XFLO + ks * 32, al);
                // xf part (bf16x3): Wo1 rows k = 128 + ks*16
                {
                    uint32_t bhA[4], bhB[4], blA[4], blB[4];
                    const uint32_t ko = (128 + ks * 16) * 2;
                    ldsm_x4(bPr264 + WO1HI + (ntg + 0) * (8 * 264 * 2) + ko, bhA);
                    ldsm_x4(bPr264 + WO1HI + (ntg + 2) * (8 * 264 * 2) + ko, bhB);
                    ldsm_x4(bPr264 + WO1LO + (ntg + 0) * (8 * 264 * 2) + ko, blA);
                    ldsm_x4(bPr264 + WO1LO + (ntg + 2) * (8 * 264 * 2) + ko, blB);
                    mma16816(acc[0], ah, bhA);  mma16816(acc[1], ah, bhA + 2);
                    mma16816(acc[2], ah, bhB);  mma16816(acc[3], ah, bhB + 2);
                    mma16816(acc[0], ah, blA);  mma16816(acc[1], ah, blA + 2);
                    mma16816(acc[2], ah, blB);  mma16816(acc[3], ah, blB + 2);
                    mma16816(acc[0], al, bhA);  mma16816(acc[1], al, bhA + 2);
                    mma16816(acc[2], al, bhB);  mma16816(acc[3], al, bhB + 2);
                }
                // axi part (plain bf16): Wo1 rows k = ks*16 (warp-uniform skip)
                if (warp_any) {
                    uint32_t bhA[4], bhB[4];
                    const uint32_t ko = (ks * 16) * 2;
                    ldsm_x4(bPr264 + WO1HI + (ntg + 0) * (8 * 264 * 2) + ko, bhA);
                    ldsm_x4(bPr264 + WO1HI + (ntg + 2) * (8 * 264 * 2) + ko, bhB);
                    mma16816(acc[0], axh[ks], bhA);  mma16816(acc[1], axh[ks], bhA + 2);
                    mma16816(acc[2], axh[ks], bhB);  mma16816(acc[3], axh[ks], bhB + 2);
                }
            }
            #pragma unroll
            for (int q = 0; q < 4; q++) {
                const int col = half * 128 + (ntg + q) * 8 + c2;
                const float g0 = fmaxf(acc[q][0] + s_bo1[col],     0.f);
                const float g1 = fmaxf(acc[q][1] + s_bo1[col + 1], 0.f);
                const float g2 = fmaxf(acc[q][2] + s_bo1[col],     0.f);
                const float g3 = fmaxf(acc[q][3] + s_bo1[col + 1], 0.f);
                rsum0 += g0 * s_wo2[col] + g1 * s_wo2[col + 1];
                rsum1 += g2 * s_wo2[col] + g3 * s_wo2[col + 1];
            }
        }
    }

    rsum0 += __shfl_xor_sync(0xffffffffu, rsum0, 1);
    rsum0 += __shfl_xor_sync(0xffffffffu, rsum0, 2);
    rsum1 += __shfl_xor_sync(0xffffffffu, rsum1, 1);
    rsum1 += __shfl_xor_sync(0xffffffffu, rsum1, 2);
    if ((lane & 3) == 0) {
        const float b2 = bo2[0];
        out[row0 + m0 + g]     = rsum0 + b2;
        out[row0 + m0 + g + 8] = rsum1 + b2;
    }
}

// ---------------------------------------------------------------------------
extern "C" void kernel_launch(void* const* d_in, const int* in_sizes, int n_in,
                              void* d_out, int out_size) {
    const float* x          = (const float*)d_in[0];
    const unsigned char* mk = (const unsigned char*)d_in[1];
    const float* Wi1        = (const float*)d_in[2];
    const float* bi1        = (const float*)d_in[3];
    const float* Wi2        = (const float*)d_in[4];
    const float* bi2        = (const float*)d_in[5];
    const float* We         = (const float*)d_in[6];
    const float* Wo1        = (const float*)d_in[7];
    const float* bo1        = (const float*)d_in[8];
    const float* Wo2        = (const float*)d_in[9];
    const float* bo2        = (const float*)d_in[10];
    float* out              = (float*)d_out;

    cudaFuncSetAttribute(k_embed_hmma, cudaFuncAttributeMaxDynamicSharedMemorySize, DSMEM);
    cudaFuncSetAttribute(k_out_hmma, cudaFuncAttributeMaxDynamicSharedMemorySize, DSMEM_OUT);

    const int prep_elems = 6 * 128 * WST + 2 * 65536;
    k_setup<<<1, 512>>>(mk);
    k_prep<<<(prep_elems + 255) / 256, 256>>>(Wi1, Wi2, We, Wo1);
    k_embed_hmma<<<RT / 128, 256, DSMEM>>>(x, bi1, bi2);
    k_out_hmma<<<RT / 128, 256, DSMEM_OUT>>>(bo1, Wo2, bo2, out);
}

// round 13
// speedup vs baseline: 1.6437x; 1.0354x over previous
#include <cuda_runtime.h>
#include <cuda_bf16.h>
#include <cstdint>

#define B_   4
#define N_   40
#define NC   64000      // 40^3
#define RT   256000     // B * N^3
#define WST  136

typedef unsigned long long u64;

// ---------------- scratch (device globals per allocation rules) ------------
__device__ float g_xembed[(size_t)RT * 128];
__device__ float g_sumexp[B_ * 128];
__device__ int   g_len[B_];
__device__ __align__(16) unsigned short g_wT[4][128 * WST];     // Wi1/Wi2 hi,lo [n][k]
__device__ __align__(16) unsigned short g_weT[2][128 * WST];    // We hi,lo [n][k]
__device__ __align__(16) unsigned short g_wo1T[2][256 * 256];   // Wo1 hi,lo [n][k]

// ---------------- helpers ---------------------------------------------------
static __device__ __forceinline__ uint32_t smem_u32(const void* p) {
    uint32_t a;
    asm("{ .reg .u64 t; cvta.to.shared.u64 t, %1; cvt.u32.u64 %0, t; }" : "=r"(a) : "l"(p));
    return a;
}
static __device__ __forceinline__ float bfhi(float f) {
    return __bfloat162float(__float2bfloat16(f));
}
static __device__ __forceinline__ uint32_t pack_bf2(float lo, float hi) {
    __nv_bfloat162 h = __floats2bfloat162_rn(lo, hi);
    return *reinterpret_cast<uint32_t*>(&h);
}
static __device__ __forceinline__ void ldsm_x4(uint32_t a, uint32_t* r) {
    asm volatile("ldmatrix.sync.aligned.m8n8.x4.shared.b16 {%0,%1,%2,%3}, [%4];"
        : "=r"(r[0]), "=r"(r[1]), "=r"(r[2]), "=r"(r[3]) : "r"(a));
}
static __device__ __forceinline__ void mma16816(float* d, const uint32_t* a, const uint32_t* b) {
    asm volatile("mma.sync.aligned.m16n8k16.row.col.f32.bf16.bf16.f32 "
        "{%0,%1,%2,%3}, {%4,%5,%6,%7}, {%8,%9}, {%0,%1,%2,%3};"
        : "+f"(d[0]), "+f"(d[1]), "+f"(d[2]), "+f"(d[3])
        : "r"(a[0]), "r"(a[1]), "r"(a[2]), "r"(a[3]), "r"(b[0]), "r"(b[1]));
}

// ---------------------------------------------------------------------------
// Kernel 0a: mask -> lengths, zero softmax denominators.
// ---------------------------------------------------------------------------
__global__ void k_setup(const unsigned char* __restrict__ mraw) {
    int t = threadIdx.x;
    if (t < B_ * 128) g_sumexp[t] = 0.f;
    if (t < B_) {
        int cnt = 0;
        if (mraw[1] != 0) {
            for (int j = 0; j < N_; j++) cnt += (mraw[t * N_ + j] != 0) ? 1 : 0;
        } else {
            const unsigned int* mi = (const unsigned int*)mraw;
            for (int j = 0; j < N_; j++) cnt += (mi[t * N_ + j] != 0u) ? 1 : 0;
        }
        g_len[t] = cnt;
    }
}

// ---------------------------------------------------------------------------
// Kernel 0b: transposed bf16 hi/lo weight images for Wi1, Wi2, We, Wo1.
// ---------------------------------------------------------------------------
__global__ void k_prep(const float* __restrict__ Wi1, const float* __restrict__ Wi2,
                       const float* __restrict__ We,  const float* __restrict__ Wo1) {
    int idx = blockIdx.x * 256 + threadIdx.x;
    if (idx < 4 * 128 * WST) {
        int mat = idx / (128 * WST);
        int r   = idx % (128 * WST);
        int n   = r / WST;
        int k   = r % WST;
        float v = 0.f;
        if (k < 128) {
            v = (mat < 2 ? Wi1 : Wi2)[k * 128 + n];
            if (mat & 1) v = v - bfhi(v);
        }
        __nv_bfloat16 h = __float2bfloat16(v);
        g_wT[mat][n * WST + k] = *reinterpret_cast<unsigned short*>(&h);
    } else if (idx < 6 * 128 * WST) {
        int r   = idx - 4 * 128 * WST;
        int img = r / (128 * WST);
        int rr  = r % (128 * WST);
        int n   = rr / WST;
        int k   = rr % WST;
        float v = 0.f;
        if (k < 128) {
            v = We[k * 128 + n];
            if (img) v = v - bfhi(v);
        }
        __nv_bfloat16 h = __float2bfloat16(v);
        g_weT[img][n * WST + k] = *reinterpret_cast<unsigned short*>(&h);
    } else if (idx < 6 * 128 * WST + 2 * 65536) {
        int r   = idx - 6 * 128 * WST;
        int img = r / 65536;
        int rr  = r % 65536;
        int n   = rr / 256;
        int k   = rr % 256;
        float v = Wo1[k * 256 + n];
        if (img) v = v - bfhi(v);
        __nv_bfloat16 h = __float2bfloat16(v);
        g_wo1T[img][n * 256 + k] = *reinterpret_cast<unsigned short*>(&h);
    }
}

// ---------------------------------------------------------------------------
// Kernel 1 (HMMA, unchanged from round-8 best): x_embed + sumexp.
// ---------------------------------------------------------------------------
#define AHI_OFF 0
#define ALO_OFF 34816
#define W_OFF   69632
#define WIMG    34816
#define SXF_STRIDE 132
#define DSMEM   208896

extern __shared__ unsigned char sdyn[];
__global__ __launch_bounds__(256, 1) void k_embed_hmma(
    const float* __restrict__ x,
    const float* __restrict__ bi1, const float* __restrict__ bi2)
{
    __shared__ float s_bias1[128], s_bias2[128];
    __shared__ unsigned char s_vf[128];

    const int t    = threadIdx.x;
    const int lane = t & 31;
    const int w    = t >> 5;
    const int row0 = blockIdx.x * 128;
    const int b    = row0 / NC;
    const uint32_t sbase = smem_u32(sdyn);

    {
        const float4* ws = (const float4*)g_wT;
        float4* wd = (float4*)(sdyn + W_OFF);
        #pragma unroll
        for (int i = 0; i < 34; i++) wd[t + i * 256] = ws[t + i * 256];
    }
    {
        const float4* xg = (const float4*)(x + (size_t)row0 * 128);
        #pragma unroll
        for (int i = 0; i < 16; i++) {
            int fidx = t + i * 256;
            float4 v = xg[fidx];
            int row = fidx >> 5;
            int k   = (fidx & 31) * 4;
            uint32_t hA = pack_bf2(v.x, v.y);
            uint32_t hB = pack_bf2(v.z, v.w);
            uint32_t lA = pack_bf2(v.x - bfhi(v.x), v.y - bfhi(v.y));
            uint32_t lB = pack_bf2(v.z - bfhi(v.z), v.w - bfhi(v.w));
            size_t off = ((size_t)row * WST + k) * 2;
            *(u64*)(sdyn + AHI_OFF + off) = ((u64)hB << 32) | hA;
            *(u64*)(sdyn + ALO_OFF + off) = ((u64)lB << 32) | lA;
        }
    }
    if (t < 128) {
        s_bias1[t] = bi1[t];
        s_bias2[t] = bi2[t];
        const int lenb = g_len[b];
        const int rem = row0 + t - b * NC;
        const int i  = rem / 1600;
        const int j  = (rem / 40) % 40;
        const int kk = rem % 40;
        s_vf[t] = (i < j) && (j < kk) && (kk < lenb);
    }
    __syncthreads();

    const int m0 = w * 16;
    const int c2 = (lane & 3) * 2;
    const uint32_t aHi = sbase + AHI_OFF + (((m0 + (lane & 15)) * WST + (lane >> 4) * 8) << 1);
    const uint32_t aLo = aHi + (ALO_OFF - AHI_OFF);
    const uint32_t bPr = sbase + W_OFF +
        (((((lane & 7) + ((lane >> 4) << 3)) * WST) + ((lane >> 3) & 1) * 8) << 1);

    float acc[16][4];
    #pragma unroll
    for (int nt = 0; nt < 16; nt++)
        acc[nt][0] = acc[nt][1] = acc[nt][2] = acc[nt][3] = 0.f;

    #pragma unroll
    for (int ks = 0; ks < 8; ks++) {
        uint32_t ahi[4], alo[4];
        ldsm_x4(aHi + ks * 32, ahi);
        ldsm_x4(aLo + ks * 32, alo);
        #pragma unroll
        for (int nt = 0; nt < 16; nt += 2) {
            uint32_t bh[4], bl[4];
            ldsm_x4(bPr + 0 * WIMG + nt * (8 * WST * 2) + ks * 32, bh);
            ldsm_x4(bPr + 1 * WIMG + nt * (8 * WST * 2) + ks * 32, bl);
            mma16816(acc[nt], ahi, bh);     mma16816(acc[nt + 1], ahi, bh + 2);
            mma16816(acc[nt], ahi, bl);     mma16816(acc[nt + 1], ahi, bl + 2);
            mma16816(acc[nt], alo, bh);     mma16816(acc[nt + 1], alo, bh + 2);
        }
    }
    __syncthreads();

    uint32_t a2h[8][4], a2l[8][4];
    #pragma unroll
    for (int ks = 0; ks < 8; ks++) {
        #pragma unroll
        for (int h = 0; h < 2; h++) {
            const int nt = 2 * ks + h;
            const float b0 = s_bias1[nt * 8 + c2];
            const float b1 = s_bias1[nt * 8 + c2 + 1];
            float f0 = fmaxf(acc[nt][0] + b0, 0.f);
            float f1 = fmaxf(acc[nt][1] + b1, 0.f);
            float f2 = fmaxf(acc[nt][2] + b0, 0.f);
            float f3 = fmaxf(acc[nt][3] + b1, 0.f);
            a2h[ks][0 + 2 * h] = pack_bf2(f0, f1);
            a2h[ks][1 + 2 * h] = pack_bf2(f2, f3);
            a2l[ks][0 + 2 * h] = pack_bf2(f0 - bfhi(f0), f1 - bfhi(f1));
            a2l[ks][1 + 2 * h] = pack_bf2(f2 - bfhi(f2), f3 - bfhi(f3));
        }
    }

    #pragma unroll
    for (int nt = 0; nt < 16; nt++)
        acc[nt][0] = acc[nt][1] = acc[nt][2] = acc[nt][3] = 0.f;
    #pragma unroll
    for (int ks = 0; ks < 8; ks++) {
        #pragma unroll
        for (int nt = 0; nt < 16; nt += 2) {
            uint32_t bh[4], bl[4];
            ldsm_x4(bPr + 2 * WIMG + nt * (8 * WST * 2) + ks * 32, bh);
            ldsm_x4(bPr + 3 * WIMG + nt * (8 * WST * 2) + ks * 32, bl);
            mma16816(acc[nt], a2h[ks], bh); mma16816(acc[nt + 1], a2h[ks], bh + 2);
            mma16816(acc[nt], a2h[ks], bl); mma16816(acc[nt + 1], a2h[ks], bl + 2);
            mma16816(acc[nt], a2l[ks], bh); mma16816(acc[nt + 1], a2l[ks], bh + 2);
        }
    }

    float* sxf = (float*)sdyn;
    const int g = lane >> 2;
    #pragma unroll
    for (int nt = 0; nt < 16; nt++) {
        const int nc = nt * 8 + c2;
        const float b0 = s_bias2[nc], b1 = s_bias2[nc + 1];
        *(float2*)(&sxf[(m0 + g) * SXF_STRIDE + nc])     = make_float2(acc[nt][0] + b0, acc[nt][1] + b1);
        *(float2*)(&sxf[(m0 + g + 8) * SXF_STRIDE + nc]) = make_float2(acc[nt][2] + b0, acc[nt][3] + b1);
    }
    __syncthreads();

    {
        float4* xo = (float4*)(g_xembed + (size_t)row0 * 128);
        #pragma unroll
        for (int i = 0; i < 16; i++) {
            int idx = t + i * 256;
            int row = idx >> 5;
            int c4  = (idx & 31) * 4;
            const float* p = &sxf[row * SXF_STRIDE + c4];
            xo[idx] = make_float4(p[0], p[1], p[2], p[3]);
        }
    }
    if (t < 128) {
        float s = 0.f;
        for (int r = 0; r < 128; r++)
            if (s_vf[r]) s += __expf(sxf[r * SXF_STRIDE + t]);
        if (s != 0.f) atomicAdd(&g_sumexp[b * 128 + t], s);
    }
}

// ---------------------------------------------------------------------------
// Kernel 2 (HMMA v4): 256 rows per CTA, warp = M32 (two m-tiles). Wo1 staged
// in 64-col quarters; every B fragment feeds 2 m-tiles -> per-row B traffic
// and copy bytes halve. Stage A plain bf16 with per-m-group gating; axi
// fragments in registers.
// ---------------------------------------------------------------------------
#define XFHI 0
#define XFLO 69632
#define WEHI 139264
#define WQHI 139264
#define WQLO 173056
#define DSMEM_OUT 206848

// copy one 64-col Wo1 quarter image into a 264-stride smem buffer.
static __device__ __forceinline__ void copy_wo1_quarter(
    unsigned char* sm, uint32_t dst0, int img, int q, int t, bool full)
{
    const uint4* src = (const uint4*)(g_wo1T[img] + (size_t)(q * 64) * 256);
    if (full) {
        #pragma unroll
        for (int i = 0; i < 8; i++) {
            int e = t + i * 256;
            int r = e >> 5;
            int kq = (e & 31) * 8;
            *(uint4*)(sm + dst0 + ((r * 264 + kq) << 1)) = src[e];
        }
    } else {
        #pragma unroll
        for (int i = 0; i < 4; i++) {
            int e = t + i * 256;
            int r = e >> 4;
            int kq = 128 + (e & 15) * 8;
            *(uint4*)(sm + dst0 + ((r * 264 + kq) << 1)) = src[r * 32 + (kq >> 3)];
        }
    }
}

__global__ __launch_bounds__(256, 1) void k_out_hmma(
    const float* __restrict__ bo1,
    const float* __restrict__ Wo2, const float* __restrict__ bo2,
    float* __restrict__ out)
{
    __shared__ float s_bo1[256], s_wo2[256], s_inv[128];
    __shared__ unsigned char s_vf[256];

    const int t    = threadIdx.x;
    const int lane = t & 31;
    const int w    = t >> 5;
    const int row0 = blockIdx.x * 256;   // 64000 % 256 == 0: no batch straddle
    const int b    = row0 / NC;
    const uint32_t sbase = smem_u32(sdyn);

    if (t < 128) s_inv[t] = 1.0f / g_sumexp[b * 128 + t];
    {
        const int lenb = g_len[b];
        const int rem = row0 + t - b * NC;
        const int i  = rem / 1600;
        const int j  = (rem / 40) % 40;
        const int kk = rem % 40;
        s_vf[t] = (i < j) && (j < kk) && (kk < lenb);
    }
    s_bo1[t] = bo1[t];
    s_wo2[t] = Wo2[t];
    const int bany = __syncthreads_or((int)s_vf[t]);

    // xf tiles (256 rows) -> bf16 hi/lo images
    {
        const float4* xg = (const float4*)(g_xembed + (size_t)row0 * 128);
        #pragma unroll
        for (int i = 0; i < 32; i++) {
            int fidx = t + i * 256;
            float4 v = xg[fidx];
            int row = fidx >> 5;
            int k   = (fidx & 31) * 4;
            uint32_t hA = pack_bf2(v.x, v.y);
            uint32_t hB = pack_bf2(v.z, v.w);
            uint32_t lA = pack_bf2(v.x - bfhi(v.x), v.y - bfhi(v.y));
            uint32_t lB = pack_bf2(v.z - bfhi(v.z), v.w - bfhi(v.w));
            size_t off = ((size_t)row * WST + k) * 2;
            *(u64*)(sdyn + XFHI + off) = ((u64)hB << 32) | hA;
            *(u64*)(sdyn + XFLO + off) = ((u64)lB << 32) | lA;
        }
    }
    // We hi image (stage A plain bf16) — only when CTA has valid rows
    if (bany) {
        const float4* ws = (const float4*)g_weT[0];
        float4* wd = (float4*)(sdyn + WEHI);
        #pragma unroll
        for (int i = 0; i < 9; i++) {
            int e = t + i * 256;
            if (e < 2176) wd[e] = ws[e];
        }
    }
    __syncthreads();

    const int c2 = (lane & 3) * 2;
    const int g  = lane >> 2;
    const uint32_t aAddr0 = sbase + XFHI + (((w * 16 + (lane & 15)) * WST + (lane >> 4) * 8) << 1);
    const uint32_t aAddr1 = aAddr0 + (128 * WST * 2);
    const uint32_t bPr136 = sbase +
        (((((lane & 7) + ((lane >> 4) << 3)) * WST) + ((lane >> 3) & 1) * 8) << 1);

    const int anyv0 = __any_sync(0xffffffffu, (int)s_vf[w * 16 + (lane & 15)]);
    const int anyv1 = __any_sync(0xffffffffu, (int)s_vf[128 + w * 16 + (lane & 15)]);

    // ---- stage A (plain bf16): axi = a .* relu(xf @ We); frags in registers ----
    uint32_t axh[2][8][4];
    if (anyv0 || anyv1) {
        #pragma unroll
        for (int ntg = 0; ntg < 16; ntg += 4) {
            float acc[2][4][4];
            #pragma unroll
            for (int mt = 0; mt < 2; mt++)
                #pragma unroll
                for (int q = 0; q < 4; q++)
                    acc[mt][q][0] = acc[mt][q][1] = acc[mt][q][2] = acc[mt][q][3] = 0.f;
            #pragma unroll
            for (int ks = 0; ks < 8; ks++) {
                uint32_t bhA[4], bhB[4];
                ldsm_x4(bPr136 + WEHI + (ntg + 0) * (8 * WST * 2) + ks * 32, bhA);
                ldsm_x4(bPr136 + WEHI + (ntg + 2) * (8 * WST * 2) + ks * 32, bhB);
                if (anyv0) {
                    uint32_t ah[4];
                    ldsm_x4(aAddr0 + ks * 32, ah);
                    mma16816(acc[0][0], ah, bhA);  mma16816(acc[0][1], ah, bhA + 2);
                    mma16816(acc[0][2], ah, bhB);  mma16816(acc[0][3], ah, bhB + 2);
                }
                if (anyv1) {
                    uint32_t ah[4];
                    ldsm_x4(aAddr1 + ks * 32, ah);
                    mma16816(acc[1][0], ah, bhA);  mma16816(acc[1][1], ah, bhA + 2);
                    mma16816(acc[1][2], ah, bhB);  mma16816(acc[1][3], ah, bhB + 2);
                }
            }
            // epilogue -> bf16 A-fragments for cols [ntg*8, ntg*8+32)
            #pragma unroll
            for (int mt = 0; mt < 2; mt++) {
                if (!(mt == 0 ? anyv0 : anyv1)) continue;
                const int r0 = mt * 128 + w * 16 + g, r1 = r0 + 8;
                const bool v0 = s_vf[r0], v1 = s_vf[r1];
                #pragma unroll
                for (int q = 0; q < 4; q++) {
                    const int nt = ntg + q;
                    const int c = nt * 8 + c2;
                    const float i0 = s_inv[c], i1 = s_inv[c + 1];
                    float v00 = 0.f, v01 = 0.f, v10 = 0.f, v11 = 0.f;
                    if (v0) {
                        __nv_bfloat162 h = *(__nv_bfloat162*)(sdyn + XFHI + ((r0 * WST + c) << 1));
                        __nv_bfloat162 l = *(__nv_bfloat162*)(sdyn + XFLO + ((r0 * WST + c) << 1));
                        float x0 = __bfloat162float(h.x) + __bfloat162float(l.x);
                        float x1 = __bfloat162float(h.y) + __bfloat162float(l.y);
                        v00 = __expf(x0) * i0 * fmaxf(acc[mt][q][0], 0.f);
                        v01 = __expf(x1) * i1 * fmaxf(acc[mt][q][1], 0.f);
                    }
                    if (v1) {
                        __nv_bfloat162 h = *(__nv_bfloat162*)(sdyn + XFHI + ((r1 * WST + c) << 1));
                        __nv_bfloat162 l = *(__nv_bfloat162*)(sdyn + XFLO + ((r1 * WST + c) << 1));
                        float x0 = __bfloat162float(h.x) + __bfloat162float(l.x);
                        float x1 = __bfloat162float(h.y) + __bfloat162float(l.y);
                        v10 = __expf(x0) * i0 * fmaxf(acc[mt][q][2], 0.f);
                        v11 = __expf(x1) * i1 * fmaxf(acc[mt][q][3], 0.f);
                    }
                    const int kst = nt >> 1;
                    const int h2  = (nt & 1) * 2;
                    axh[mt][kst][0 + h2] = pack_bf2(v00, v01);
                    axh[mt][kst][1 + h2] = pack_bf2(v10, v11);
                }
            }
        }
    }

    // ---- stage B: four 64-col quarters of Wo1; B frags shared by 2 m-tiles ----
    float rs[2][2];
    rs[0][0] = rs[0][1] = rs[1][0] = rs[1][1] = 0.f;
    const uint32_t bPr264 = sbase +
        (((((lane & 7) + ((lane >> 4) << 3)) * 264) + ((lane >> 3) & 1) * 8) << 1);

    #pragma unroll
    for (int q4 = 0; q4 < 4; q4++) {
        __syncthreads();   // prior reads of the quarter region (or WE) complete
        copy_wo1_quarter(sdyn, WQHI, 0, q4, t, bany != 0);
        copy_wo1_quarter(sdyn, WQLO, 1, q4, t, bany != 0);
        __syncthreads();

        #pragma unroll
        for (int ntg = 0; ntg < 8; ntg += 4) {
            float acc[2][4][4];
            #pragma unroll
            for (int mt = 0; mt < 2; mt++)
                #pragma unroll
                for (int q = 0; q < 4; q++)
                    acc[mt][q][0] = acc[mt][q][1] = acc[mt][q][2] = acc[mt][q][3] = 0.f;
            #pragma unroll
            for (int ks = 0; ks < 8; ks++) {
                uint32_t ah0[4], al0[4], ah1[4], al1[4];
                ldsm_x4(aAddr0 + ks * 32, ah0);
                ldsm_x4(aAddr0 + (XFLO - XFHI) + ks * 32, al0);
                ldsm_x4(aAddr1 + ks * 32, ah1);
                ldsm_x4(aAddr1 + (XFLO - XFHI) + ks * 32, al1);
                // xf part (bf16x3): Wo1 rows k = 128 + ks*16
                {
                    uint32_t bhA[4], bhB[4], blA[4], blB[4];
                    const uint32_t ko = (128 + ks * 16) * 2;
                    ldsm_x4(bPr264 + WQHI + (ntg + 0) * (8 * 264 * 2) + ko, bhA);
                    ldsm_x4(bPr264 + WQHI + (ntg + 2) * (8 * 264 * 2) + ko, bhB);
                    ldsm_x4(bPr264 + WQLO + (ntg + 0) * (8 * 264 * 2) + ko, blA);
                    ldsm_x4(bPr264 + WQLO + (ntg + 2) * (8 * 264 * 2) + ko, blB);
                    mma16816(acc[0][0], ah0, bhA);  mma16816(acc[0][1], ah0, bhA + 2);
                    mma16816(acc[0][2], ah0, bhB);  mma16816(acc[0][3], ah0, bhB + 2);
                    mma16816(acc[1][0], ah1, bhA);  mma16816(acc[1][1], ah1, bhA + 2);
                    mma16816(acc[1][2], ah1, bhB);  mma16816(acc[1][3], ah1, bhB + 2);
                    mma16816(acc[0][0], ah0, blA);  mma16816(acc[0][1], ah0, blA + 2);
                    mma16816(acc[0][2], ah0, blB);  mma16816(acc[0][3], ah0, blB + 2);
                    mma16816(acc[1][0], ah1, blA);  mma16816(acc[1][1], ah1, blA + 2);
                    mma16816(acc[1][2], ah1, blB);  mma16816(acc[1][3], ah1, blB + 2);
                    mma16816(acc[0][0], al0, bhA);  mma16816(acc[0][1], al0, bhA + 2);
                    mma16816(acc[0][2], al0, bhB);  mma16816(acc[0][3], al0, bhB + 2);
                    mma16816(acc[1][0], al1, bhA);  mma16816(acc[1][1], al1, bhA + 2);
                    mma16816(acc[1][2], al1, bhB);  mma16816(acc[1][3], al1, bhB + 2);
                }
                // axi part (plain bf16): Wo1 rows k = ks*16, gated per m-group
                if (anyv0 || anyv1) {
                    uint32_t bhA[4], bhB[4];
                    const uint32_t ko = (ks * 16) * 2;
                    ldsm_x4(bPr264 + WQHI + (ntg + 0) * (8 * 264 * 2) + ko, bhA);
                    ldsm_x4(bPr264 + WQHI + (ntg + 2) * (8 * 264 * 2) + ko, bhB);
                    if (anyv0) {
                        mma16816(acc[0][0], axh[0][ks], bhA);  mma16816(acc[0][1], axh[0][ks], bhA + 2);
                        mma16816(acc[0][2], axh[0][ks], bhB);  mma16816(acc[0][3], axh[0][ks], bhB + 2);
                    }
                    if (anyv1) {
                        mma16816(acc[1][0], axh[1][ks], bhA);  mma16816(acc[1][1], axh[1][ks], bhA + 2);
                        mma16816(acc[1][2], axh[1][ks], bhB);  mma16816(acc[1][3], axh[1][ks], bhB + 2);
                    }
                }
            }
            #pragma unroll
            for (int mt = 0; mt < 2; mt++)
                #pragma unroll
                for (int q = 0; q < 4; q++) {
                    const int col = q4 * 64 + (ntg + q) * 8 + c2;
                    const float g0 = fmaxf(acc[mt][q][0] + s_bo1[col],     0.f);
                    const float g1 = fmaxf(acc[mt][q][1] + s_bo1[col + 1], 0.f);
                    const float g2 = fmaxf(acc[mt][q][2] + s_bo1[col],     0.f);
                    const float g3 = fmaxf(acc[mt][q][3] + s_bo1[col + 1], 0.f);
                    rs[mt][0] += g0 * s_wo2[col] + g1 * s_wo2[col + 1];
                    rs[mt][1] += g2 * s_wo2[col] + g3 * s_wo2[col + 1];
                }
        }
    }

    #pragma unroll
    for (int mt = 0; mt < 2; mt++) {
        rs[mt][0] += __shfl_xor_sync(0xffffffffu, rs[mt][0], 1);
        rs[mt][0] += __shfl_xor_sync(0xffffffffu, rs[mt][0], 2);
        rs[mt][1] += __shfl_xor_sync(0xffffffffu, rs[mt][1], 1);
        rs[mt][1] += __shfl_xor_sync(0xffffffffu, rs[mt][1], 2);
    }
    if ((lane & 3) == 0) {
        const float b2 = bo2[0];
        #pragma unroll
        for (int mt = 0; mt < 2; mt++) {
            out[row0 + mt * 128 + w * 16 + g]     = rs[mt][0] + b2;
            out[row0 + mt * 128 + w * 16 + g + 8] = rs[mt][1] + b2;
        }
    }
}

// ---------------------------------------------------------------------------
extern "C" void kernel_launch(void* const* d_in, const int* in_sizes, int n_in,
                              void* d_out, int out_size) {
    const float* x          = (const float*)d_in[0];
    const unsigned char* mk = (const unsigned char*)d_in[1];
    const float* Wi1        = (const float*)d_in[2];
    const float* bi1        = (const float*)d_in[3];
    const float* Wi2        = (const float*)d_in[4];
    const float* bi2        = (const float*)d_in[5];
    const float* We         = (const float*)d_in[6];
    const float* Wo1        = (const float*)d_in[7];
    const float* bo1        = (const float*)d_in[8];
    const float* Wo2        = (const float*)d_in[9];
    const float* bo2        = (const float*)d_in[10];
    float* out              = (float*)d_out;

    cudaFuncSetAttribute(k_embed_hmma, cudaFuncAttributeMaxDynamicSharedMemorySize, DSMEM);
    cudaFuncSetAttribute(k_out_hmma, cudaFuncAttributeMaxDynamicSharedMemorySize, DSMEM_OUT);

    const int prep_elems = 6 * 128 * WST + 2 * 65536;
    k_setup<<<1, 512>>>(mk);
    k_prep<<<(prep_elems + 255) / 256, 256>>>(Wi1, Wi2, We, Wo1);
    k_embed_hmma<<<RT / 128, 256, DSMEM>>>(x, bi1, bi2);
    k_out_hmma<<<RT / 256, 256, DSMEM_OUT>>>(bo1, Wo2, bo2, out);
}